// round 7
// baseline (speedup 1.0000x reference)
#include <cuda_runtime.h>
#include <cuda_fp16.h>
#include <math.h>

#define BB 4
#define NN 10000
#define EE 160000
#define CC 128
#define ITERS 3
#define M_TOTAL (BB * NN)          // 40000 rows, = 1250 * 32 exactly
#define TM 32
#define GEMM_THREADS 256
#define GEMM_SMEM_BYTES ((TM * 2 * CC + CC * CC) * 4)   // 32KB dup-X + 64KB W = 96KB

// ---------------- scratch (static device globals; no runtime allocation) ----
__device__ __align__(16) float g_EA [M_TOTAL * CC];      // exp(states@Wsa + att_b)
__device__ __align__(16) __half g_T[M_TOTAL * 2 * CC];   // per node: [EL(128) | ELS(128)] fp16
__device__ __align__(16) float g_G  [M_TOTAL * CC];      // linked_gated
__device__ __align__(16) float g_SS [M_TOTAL * CC];      // states / norm
__device__ int g_deg[M_TOTAL];
__device__ int g_cur[M_TOTAL];
__device__ int g_off[BB * (NN + 1)];
__device__ int g_adj[BB * 2 * EE];

// ---------------- CSR build ------------------------------------------------
__global__ void zero_deg_kernel() {
    int i = blockIdx.x * blockDim.x + threadIdx.x;
    if (i < M_TOTAL) g_deg[i] = 0;
}

__global__ void count_kernel(const int* __restrict__ conn) {
    int idx = blockIdx.x * blockDim.x + threadIdx.x;
    if (idx >= BB * EE) return;
    int b = idx / EE;
    int2 uv = ((const int2*)conn)[idx];
    atomicAdd(&g_deg[b * NN + uv.x], 1);
    atomicAdd(&g_deg[b * NN + uv.y], 1);
}

// one block (1024 threads) per batch: exclusive scan of degrees -> offsets
__global__ void scan_kernel() {
    const int CH = 10;                       // 1024*10 >= 10000
    int b = blockIdx.x;
    int t = threadIdx.x;
    int base = t * CH;
    int pref[CH];
    int s = 0;
#pragma unroll
    for (int i = 0; i < CH; i++) {
        int idx = base + i;
        int v = (idx < NN) ? g_deg[b * NN + idx] : 0;
        pref[i] = s;
        s += v;
    }
    int lane = t & 31, wid = t >> 5;
    int inc = s;
#pragma unroll
    for (int o = 1; o < 32; o <<= 1) {
        int n = __shfl_up_sync(0xffffffffu, inc, o);
        if (lane >= o) inc += n;
    }
    __shared__ int wtot[32];
    if (lane == 31) wtot[wid] = inc;
    __syncthreads();
    if (wid == 0) {
        int v = wtot[lane];
        int iv = v;
#pragma unroll
        for (int o = 1; o < 32; o <<= 1) {
            int n = __shfl_up_sync(0xffffffffu, iv, o);
            if (lane >= o) iv += n;
        }
        wtot[lane] = iv - v;                  // warp-exclusive offset
    }
    __syncthreads();
    int texcl = wtot[wid] + (inc - s);        // thread-exclusive offset
#pragma unroll
    for (int i = 0; i < CH; i++) {
        int idx = base + i;
        if (idx < NN) {
            int o = texcl + pref[i];
            g_off[b * (NN + 1) + idx] = o;
            g_cur[b * NN + idx] = o;
        }
    }
    if (t == blockDim.x - 1) g_off[b * (NN + 1) + NN] = texcl + s;
}

__global__ void fill_kernel(const int* __restrict__ conn) {
    int idx = blockIdx.x * blockDim.x + threadIdx.x;
    if (idx >= BB * EE) return;
    int b = idx / EE;
    int2 uv = ((const int2*)conn)[idx];
    int p = atomicAdd(&g_cur[b * NN + uv.x], 1);
    g_adj[b * 2 * EE + p] = uv.y;
    int q = atomicAdd(&g_cur[b * NN + uv.y], 1);
    g_adj[b * 2 * EE + q] = uv.x;
}

// ---------------- GEMM [40000,128] x [128,128], FFMA2 mainloop -------------
// Xs is stored DUPLICATED: element (row,k) occupies floats [row*256+2k, row*256+2k+1]
// (both copies equal) so the broadcast operand loads as one LDS.64 f32x2.
// MODE 0: O1 = tanh(acc + bias)                        (init states; X=objects)
// MODE 1: O1 = exp(acc + bias)                         (EA)
// MODE 2: T[row] = { fp16(exp(acc)), fp16(exp(acc)*X[row][c]) }   (EL|ELS combined)
// MODE 3: O1 = tanh(acc + add[row][c] + bias)          (state update; X=G, add=SS)
template <int MODE>
__global__ void gemm_k(const float* __restrict__ X, const float* __restrict__ W,
                       const float* __restrict__ bias, const float* __restrict__ add,
                       float* __restrict__ O1, __half* __restrict__ OT) {
    extern __shared__ float sm[];
    float* Xs = sm;                   // TM x CC duplicated  (TM*2*CC floats)
    float* Ws = sm + TM * 2 * CC;     // CC x CC row-major (k-major)
    int t = threadIdx.x;
    int block_row = blockIdx.x * TM;

    // load W: 16384 floats = 4096 float4, 16 per thread
    const float4* W4 = (const float4*)W;
    float4* Ws4 = (float4*)Ws;
#pragma unroll
    for (int i = 0; i < 16; i++) Ws4[t + 256 * i] = W4[t + 256 * i];

    // load X tile (32x128) and store duplicated: 4 float4 per thread
    const float4* X4 = (const float4*)(X + (size_t)block_row * CC);
    float4* Xsd4 = (float4*)Xs;
#pragma unroll
    for (int i = 0; i < 4; i++) {
        float4 v = X4[t + 256 * i];
        int e = (t + 256 * i) * 4;           // element index (row*128 + k)
        Xsd4[e / 2]     = make_float4(v.x, v.x, v.y, v.y);
        Xsd4[e / 2 + 1] = make_float4(v.z, v.z, v.w, v.w);
    }
    __syncthreads();

    int tx = t & 31, ty = t >> 5;            // tx: col group (4 cols), ty: row group (4 rows)
    unsigned long long acc[4][2];
#pragma unroll
    for (int r = 0; r < 4; r++) { acc[r][0] = 0ull; acc[r][1] = 0ull; }

    // ULL view of dup-X: element (row,k) at index row*128 + k
    const unsigned long long* Xd =
        (const unsigned long long*)Xs + (size_t)(ty * 4) * CC;

#pragma unroll 8
    for (int k = 0; k < CC; k++) {
        ulonglong2 w2 = *(const ulonglong2*)&Ws[k * CC + tx * 4];  // (w0,w1),(w2,w3)
#pragma unroll
        for (int r = 0; r < 4; r++) {
            unsigned long long x2 = Xd[r * CC + k];                // {x,x} broadcast
            asm("fma.rn.f32x2 %0, %1, %2, %0;" : "+l"(acc[r][0]) : "l"(x2), "l"(w2.x));
            asm("fma.rn.f32x2 %0, %1, %2, %0;" : "+l"(acc[r][1]) : "l"(x2), "l"(w2.y));
        }
    }

    int c0 = tx * 4;
    float4 bz = make_float4(0.f, 0.f, 0.f, 0.f);
    if (MODE == 0 || MODE == 1 || MODE == 3) bz = *(const float4*)&bias[c0];

#pragma unroll
    for (int r = 0; r < 4; r++) {
        int lrow = ty * 4 + r;
        size_t grow = (size_t)(block_row + lrow);
        float2 p0 = *(float2*)&acc[r][0];
        float2 p1 = *(float2*)&acc[r][1];
        float a0 = p0.x, a1 = p0.y, a2 = p1.x, a3 = p1.y;
        if (MODE == 0) {
            float4 o;
            o.x = tanhf(a0 + bz.x); o.y = tanhf(a1 + bz.y);
            o.z = tanhf(a2 + bz.z); o.w = tanhf(a3 + bz.w);
            *(float4*)&O1[grow * CC + c0] = o;
        } else if (MODE == 1) {
            float4 o;
            o.x = __expf(a0 + bz.x); o.y = __expf(a1 + bz.y);
            o.z = __expf(a2 + bz.z); o.w = __expf(a3 + bz.w);
            *(float4*)&O1[grow * CC + c0] = o;
        } else if (MODE == 2) {
            float el0 = __expf(a0), el1 = __expf(a1);
            float el2 = __expf(a2), el3 = __expf(a3);
            // states from dup-X: element (lrow, c) at float index lrow*256 + 2c
            float s0 = Xs[lrow * 256 + 2 * (c0 + 0)];
            float s1 = Xs[lrow * 256 + 2 * (c0 + 1)];
            float s2 = Xs[lrow * 256 + 2 * (c0 + 2)];
            float s3 = Xs[lrow * 256 + 2 * (c0 + 3)];
            __half2 e01 = __floats2half2_rn(el0, el1);
            __half2 e23 = __floats2half2_rn(el2, el3);
            __half2 q01 = __floats2half2_rn(el0 * s0, el1 * s1);
            __half2 q23 = __floats2half2_rn(el2 * s2, el3 * s3);
            uint2 pe, ps;
            pe.x = *(unsigned int*)&e01; pe.y = *(unsigned int*)&e23;
            ps.x = *(unsigned int*)&q01; ps.y = *(unsigned int*)&q23;
            *(uint2*)&OT[grow * 2 * CC + c0]      = pe;
            *(uint2*)&OT[grow * 2 * CC + CC + c0] = ps;
        } else {  // MODE 3
            float4 ad = *(const float4*)&add[grow * CC + c0];
            float4 o;
            o.x = tanhf(a0 + ad.x + bz.x); o.y = tanhf(a1 + ad.y + bz.y);
            o.z = tanhf(a2 + ad.z + bz.z); o.w = tanhf(a3 + ad.w + bz.w);
            *(float4*)&O1[grow * CC + c0] = o;
        }
    }
}

// ---------------- per-node aggregation (one warp per node, no atomics) -----
// Combined fp16 table: one LDG.128 per edge per warp fetches EL|ELS (512B).
// Lanes 0-15 accumulate EL channels (8 each), lanes 16-31 accumulate ELS.
__device__ __forceinline__ void acc8_fp16(float* acc, uint4 v) {
    unsigned int u[4] = {v.x, v.y, v.z, v.w};
#pragma unroll
    for (int q = 0; q < 4; q++) {
        float2 f = __half22float2(*(__half2*)&u[q]);
        acc[2 * q]     += f.x;
        acc[2 * q + 1] += f.y;
    }
}

__global__ void agg_kernel(const float* __restrict__ states) {
    int gw = (blockIdx.x * blockDim.x + threadIdx.x) >> 5;
    int lane = threadIdx.x & 31;
    if (gw >= M_TOTAL) return;
    int b = gw / NN;
    int i = gw - b * NN;

    int e  = g_off[b * (NN + 1) + i];
    int e2 = g_off[b * (NN + 1) + i + 1];
    const int* __restrict__ adj = g_adj + (size_t)b * 2 * EE;
    const uint4* __restrict__ T4 = (const uint4*)(g_T + (size_t)b * NN * 2 * CC);

    float acc[8];
#pragma unroll
    for (int k = 0; k < 8; k++) acc[k] = 0.f;

    for (; e + 4 <= e2; e += 4) {
        int j0 = __ldg(adj + e);
        int j1 = __ldg(adj + e + 1);
        int j2 = __ldg(adj + e + 2);
        int j3 = __ldg(adj + e + 3);
        uint4 t0 = T4[(size_t)j0 * 32 + lane];
        uint4 t1 = T4[(size_t)j1 * 32 + lane];
        uint4 t2 = T4[(size_t)j2 * 32 + lane];
        uint4 t3 = T4[(size_t)j3 * 32 + lane];
        acc8_fp16(acc, t0);
        acc8_fp16(acc, t1);
        acc8_fp16(acc, t2);
        acc8_fp16(acc, t3);
    }
    for (; e < e2; e++) {
        int j = __ldg(adj + e);
        uint4 t = T4[(size_t)j * 32 + lane];
        acc8_fp16(acc, t);
    }

    // exchange halves: lanes<16 hold sum(EL), lanes>=16 hold sum(ELS)
    float other[8];
#pragma unroll
    for (int k = 0; k < 8; k++)
        other[k] = __shfl_xor_sync(0xffffffffu, acc[k], 16);

    int sub = lane & 15;                      // channel group: c = sub*8 .. +7
    size_t rowf4 = (size_t)gw * 32 + sub * 2; // float4 index into [M_TOTAL, CC]
    float4 ea0 = ((const float4*)g_EA)[rowf4];
    float4 ea1 = ((const float4*)g_EA)[rowf4 + 1];
    float ea[8] = {ea0.x, ea0.y, ea0.z, ea0.w, ea1.x, ea1.y, ea1.z, ea1.w};

    float sE[8], sS[8];
    if (lane < 16) {
#pragma unroll
        for (int k = 0; k < 8; k++) { sE[k] = acc[k]; sS[k] = other[k]; }
    } else {
#pragma unroll
        for (int k = 0; k < 8; k++) { sE[k] = other[k]; sS[k] = acc[k]; }
    }

    float inv[8];
#pragma unroll
    for (int k = 0; k < 8; k++) inv[k] = 1.f / (1.f + ea[k] * sE[k]);

    if (lane < 16) {
        // write G = ea * sS * inv
        float4 G0, G1;
        G0.x = ea[0] * sS[0] * inv[0]; G0.y = ea[1] * sS[1] * inv[1];
        G0.z = ea[2] * sS[2] * inv[2]; G0.w = ea[3] * sS[3] * inv[3];
        G1.x = ea[4] * sS[4] * inv[4]; G1.y = ea[5] * sS[5] * inv[5];
        G1.z = ea[6] * sS[6] * inv[6]; G1.w = ea[7] * sS[7] * inv[7];
        ((float4*)g_G)[rowf4]     = G0;
        ((float4*)g_G)[rowf4 + 1] = G1;
    } else {
        // write SS = states * inv
        float4 st0 = ((const float4*)states)[rowf4];
        float4 st1 = ((const float4*)states)[rowf4 + 1];
        float4 S0, S1;
        S0.x = st0.x * inv[0]; S0.y = st0.y * inv[1];
        S0.z = st0.z * inv[2]; S0.w = st0.w * inv[3];
        S1.x = st1.x * inv[4]; S1.y = st1.y * inv[5];
        S1.z = st1.z * inv[6]; S1.w = st1.w * inv[7];
        ((float4*)g_SS)[rowf4]     = S0;
        ((float4*)g_SS)[rowf4 + 1] = S1;
    }
}

// ---------------- launch ----------------------------------------------------
extern "C" void kernel_launch(void* const* d_in, const int* in_sizes, int n_in,
                              void* d_out, int out_size) {
    const float* objects = (const float*)d_in[0];
    const float* Wos     = (const float*)d_in[1];
    const float* Wsa     = (const float*)d_in[2];
    const float* Wla     = (const float*)d_in[3];
    const float* att_b   = (const float*)d_in[4];
    const float* Wl      = (const float*)d_in[5];
    const float* st_b    = (const float*)d_in[6];
    const int*   conn    = (const int*)d_in[7];
    float* states = (float*)d_out;            // live states buffer, [B,N,C]

    cudaFuncSetAttribute(gemm_k<0>, cudaFuncAttributeMaxDynamicSharedMemorySize, GEMM_SMEM_BYTES);
    cudaFuncSetAttribute(gemm_k<1>, cudaFuncAttributeMaxDynamicSharedMemorySize, GEMM_SMEM_BYTES);
    cudaFuncSetAttribute(gemm_k<2>, cudaFuncAttributeMaxDynamicSharedMemorySize, GEMM_SMEM_BYTES);
    cudaFuncSetAttribute(gemm_k<3>, cudaFuncAttributeMaxDynamicSharedMemorySize, GEMM_SMEM_BYTES);

    float *pEA, *pG, *pSS;
    __half* pT;
    cudaGetSymbolAddress((void**)&pEA, g_EA);
    cudaGetSymbolAddress((void**)&pT,  g_T);
    cudaGetSymbolAddress((void**)&pG,  g_G);
    cudaGetSymbolAddress((void**)&pSS, g_SS);

    const int EDGE_BLOCKS = (BB * EE + 255) / 256;      // 2500
    const int GEMM_GRID   = M_TOTAL / TM;               // 1250
    const int AGG_GRID    = (M_TOTAL * 32 + 255) / 256; // 5000

    // CSR build (per launch; connections are an input)
    zero_deg_kernel<<<(M_TOTAL + 255) / 256, 256>>>();
    count_kernel<<<EDGE_BLOCKS, 256>>>(conn);
    scan_kernel<<<BB, 1024>>>();
    fill_kernel<<<EDGE_BLOCKS, 256>>>(conn);

    // init states = tanh(objects @ Wos + st_b)
    gemm_k<0><<<GEMM_GRID, GEMM_THREADS, GEMM_SMEM_BYTES>>>(objects, Wos, st_b, nullptr, states, nullptr);

    for (int it = 0; it < ITERS; it++) {
        gemm_k<1><<<GEMM_GRID, GEMM_THREADS, GEMM_SMEM_BYTES>>>(states, Wsa, att_b, nullptr, pEA, nullptr);
        gemm_k<2><<<GEMM_GRID, GEMM_THREADS, GEMM_SMEM_BYTES>>>(states, Wla, nullptr, nullptr, nullptr, pT);
        agg_kernel<<<AGG_GRID, 256>>>(states);
        gemm_k<3><<<GEMM_GRID, GEMM_THREADS, GEMM_SMEM_BYTES>>>(pG, Wl, st_b, pSS, states, nullptr);
    }
}

// round 8
// speedup vs baseline: 1.2818x; 1.2818x over previous
#include <cuda_runtime.h>
#include <cuda_fp16.h>
#include <math.h>

#define BB 4
#define NN 10000
#define EE 160000
#define CC 128
#define ITERS 3
#define M_TOTAL (BB * NN)          // 40000 rows, = 625 * 64 exactly
#define TM 64
#define GEMM_THREADS 256
#define GEMM_SMEM_BYTES ((TM * CC + CC * CC) * 4)   // 96 KB
#define PADJ (2 * EE + 8 * NN)     // 400000 padded adjacency slots per batch
#define DUMMY NN                   // per-batch zero row index in g_T

// ---------------- scratch (static device globals; no runtime allocation) ----
__device__ __align__(16) float g_EA [M_TOTAL * CC];              // exp(states@Wsa + att_b)
__device__ __align__(16) __half g_T[BB * (NN + 1) * 2 * CC];     // per node: [EL|ELS] fp16; row NN = zeros
__device__ __align__(16) float g_G  [M_TOTAL * CC];              // linked_gated
__device__ __align__(16) float g_SS [M_TOTAL * CC];              // states / norm
__device__ int g_deg[M_TOTAL];
__device__ int g_cur[M_TOTAL];
__device__ int g_off[BB * (NN + 1)];
__device__ int g_adj[BB * PADJ];

// ---------------- init: zero degrees, DUMMY-fill adj, zero dummy T rows ----
__global__ void init_kernel() {
    int i = blockIdx.x * blockDim.x + threadIdx.x;
    if (i < BB * PADJ) g_adj[i] = DUMMY;
    if (i < M_TOTAL) g_deg[i] = 0;
    if (i < BB * 128) {                     // 4 dummy rows x 128 uint32 (256 halves)
        int b = i >> 7, q = i & 127;
        ((unsigned int*)g_T)[((size_t)b * (NN + 1) + NN) * 128 + q] = 0u;
    }
}

__global__ void count_kernel(const int* __restrict__ conn) {
    int idx = blockIdx.x * blockDim.x + threadIdx.x;
    if (idx >= BB * EE) return;
    int b = idx / EE;
    int2 uv = ((const int2*)conn)[idx];
    atomicAdd(&g_deg[b * NN + uv.x], 1);
    atomicAdd(&g_deg[b * NN + uv.y], 1);
}

// one block (1024 threads) per batch: exclusive scan of degrees (padded to 8)
__global__ void scan_kernel() {
    const int CH = 10;                       // 1024*10 >= 10000
    int b = blockIdx.x;
    int t = threadIdx.x;
    int base = t * CH;
    int pref[CH];
    int s = 0;
#pragma unroll
    for (int i = 0; i < CH; i++) {
        int idx = base + i;
        int v = (idx < NN) ? ((g_deg[b * NN + idx] + 7) & ~7) : 0;  // pad to 8
        pref[i] = s;
        s += v;
    }
    int lane = t & 31, wid = t >> 5;
    int inc = s;
#pragma unroll
    for (int o = 1; o < 32; o <<= 1) {
        int n = __shfl_up_sync(0xffffffffu, inc, o);
        if (lane >= o) inc += n;
    }
    __shared__ int wtot[32];
    if (lane == 31) wtot[wid] = inc;
    __syncthreads();
    if (wid == 0) {
        int v = wtot[lane];
        int iv = v;
#pragma unroll
        for (int o = 1; o < 32; o <<= 1) {
            int n = __shfl_up_sync(0xffffffffu, iv, o);
            if (lane >= o) iv += n;
        }
        wtot[lane] = iv - v;                  // warp-exclusive offset
    }
    __syncthreads();
    int texcl = wtot[wid] + (inc - s);        // thread-exclusive offset
#pragma unroll
    for (int i = 0; i < CH; i++) {
        int idx = base + i;
        if (idx < NN) {
            int o = texcl + pref[i];
            g_off[b * (NN + 1) + idx] = o;
            g_cur[b * NN + idx] = o;
        }
    }
    if (t == blockDim.x - 1) g_off[b * (NN + 1) + NN] = texcl + s;
}

__global__ void fill_kernel(const int* __restrict__ conn) {
    int idx = blockIdx.x * blockDim.x + threadIdx.x;
    if (idx >= BB * EE) return;
    int b = idx / EE;
    int2 uv = ((const int2*)conn)[idx];
    int p = atomicAdd(&g_cur[b * NN + uv.x], 1);
    g_adj[(size_t)b * PADJ + p] = uv.y;
    int q = atomicAdd(&g_cur[b * NN + uv.y], 1);
    g_adj[(size_t)b * PADJ + q] = uv.x;
}

// ---------------- GEMM [40000,128] x [128,128] with fused epilogues --------
// (proven R6 version; exact fp32 FFMA)
// MODE 0: O1 = tanh(acc + bias)                        (init states; X=objects)
// MODE 1: O1 = exp(acc + bias)                         (EA)
// MODE 2: T[trow] = { fp16(exp(acc)), fp16(exp(acc)*X[row][c]) }  (EL|ELS; trow skips dummy rows)
// MODE 3: O1 = tanh(acc + add[row][c] + bias)          (state update; X=G, add=SS)
template <int MODE>
__global__ void gemm_k(const float* __restrict__ X, const float* __restrict__ W,
                       const float* __restrict__ bias, const float* __restrict__ add,
                       float* __restrict__ O1, __half* __restrict__ OT) {
    extern __shared__ float sm[];
    float* Xs = sm;               // TM x CC
    float* Ws = sm + TM * CC;     // CC x CC
    int t = threadIdx.x;
    int block_row = blockIdx.x * TM;

    const float4* W4 = (const float4*)W;
    float4* Ws4 = (float4*)Ws;
#pragma unroll
    for (int i = 0; i < 16; i++) Ws4[t + 256 * i] = W4[t + 256 * i];

    const float4* X4 = (const float4*)(X + (size_t)block_row * CC);
    float4* Xs4 = (float4*)Xs;
#pragma unroll
    for (int i = 0; i < 8; i++) Xs4[t + 256 * i] = X4[t + 256 * i];
    __syncthreads();

    int tx = t & 31, ty = t >> 5;           // tx: col group, ty: row group
    float acc[8][4];
#pragma unroll
    for (int r = 0; r < 8; r++) {
        acc[r][0] = 0.f; acc[r][1] = 0.f; acc[r][2] = 0.f; acc[r][3] = 0.f;
    }

#pragma unroll 8
    for (int k = 0; k < CC; k++) {
        float4 w = *(const float4*)&Ws[k * CC + tx * 4];
#pragma unroll
        for (int r = 0; r < 8; r++) {
            float x = Xs[(ty * 8 + r) * CC + k];
            acc[r][0] = fmaf(x, w.x, acc[r][0]);
            acc[r][1] = fmaf(x, w.y, acc[r][1]);
            acc[r][2] = fmaf(x, w.z, acc[r][2]);
            acc[r][3] = fmaf(x, w.w, acc[r][3]);
        }
    }

    int c0 = tx * 4;
    float4 bz = make_float4(0.f, 0.f, 0.f, 0.f);
    if (MODE == 0 || MODE == 1 || MODE == 3) bz = *(const float4*)&bias[c0];

#pragma unroll
    for (int r = 0; r < 8; r++) {
        size_t grow = (size_t)(block_row + ty * 8 + r);
        if (MODE == 0) {
            float4 o;
            o.x = tanhf(acc[r][0] + bz.x);
            o.y = tanhf(acc[r][1] + bz.y);
            o.z = tanhf(acc[r][2] + bz.z);
            o.w = tanhf(acc[r][3] + bz.w);
            *(float4*)&O1[grow * CC + c0] = o;
        } else if (MODE == 1) {
            float4 o;
            o.x = __expf(acc[r][0] + bz.x);
            o.y = __expf(acc[r][1] + bz.y);
            o.z = __expf(acc[r][2] + bz.z);
            o.w = __expf(acc[r][3] + bz.w);
            *(float4*)&O1[grow * CC + c0] = o;
        } else if (MODE == 2) {
            float el0 = __expf(acc[r][0]);
            float el1 = __expf(acc[r][1]);
            float el2 = __expf(acc[r][2]);
            float el3 = __expf(acc[r][3]);
            float4 st = *(const float4*)&Xs[(ty * 8 + r) * CC + c0];
            __half2 e01 = __floats2half2_rn(el0, el1);
            __half2 e23 = __floats2half2_rn(el2, el3);
            __half2 s01 = __floats2half2_rn(el0 * st.x, el1 * st.y);
            __half2 s23 = __floats2half2_rn(el2 * st.z, el3 * st.w);
            uint2 pe, ps;
            pe.x = *(unsigned int*)&e01; pe.y = *(unsigned int*)&e23;
            ps.x = *(unsigned int*)&s01; ps.y = *(unsigned int*)&s23;
            // skip one dummy row per preceding batch: trow = grow + grow/NN
            size_t trow = grow + (size_t)(grow / NN);
            *(uint2*)&OT[trow * 2 * CC + c0]      = pe;
            *(uint2*)&OT[trow * 2 * CC + CC + c0] = ps;
        } else {  // MODE 3
            float4 ad = *(const float4*)&add[grow * CC + c0];
            float4 o;
            o.x = tanhf(acc[r][0] + ad.x + bz.x);
            o.y = tanhf(acc[r][1] + ad.y + bz.y);
            o.z = tanhf(acc[r][2] + ad.z + bz.z);
            o.w = tanhf(acc[r][3] + ad.w + bz.w);
            *(float4*)&O1[grow * CC + c0] = o;
        }
    }
}

// ---------------- per-node aggregation (one warp per node, no atomics) -----
// Padded CSR (multiple of 8, DUMMY -> zero row): no tail, no divergence,
// 8 uint4 gathers + 2 int4 index loads in flight per iteration.
__device__ __forceinline__ void acc8_fp16(float* acc, uint4 v) {
    unsigned int u[4] = {v.x, v.y, v.z, v.w};
#pragma unroll
    for (int q = 0; q < 4; q++) {
        float2 f = __half22float2(*(__half2*)&u[q]);
        acc[2 * q]     += f.x;
        acc[2 * q + 1] += f.y;
    }
}

__global__ void agg_kernel(const float* __restrict__ states) {
    int gw = (blockIdx.x * blockDim.x + threadIdx.x) >> 5;
    int lane = threadIdx.x & 31;
    if (gw >= M_TOTAL) return;
    int b = gw / NN;
    int i = gw - b * NN;

    int e  = g_off[b * (NN + 1) + i];
    int e2 = g_off[b * (NN + 1) + i + 1];
    const int4* __restrict__ adj4 = (const int4*)(g_adj + (size_t)b * PADJ);
    const uint4* __restrict__ T4 = (const uint4*)g_T + (size_t)b * (NN + 1) * 32;

    float acc[8];
#pragma unroll
    for (int k = 0; k < 8; k++) acc[k] = 0.f;

    for (; e < e2; e += 8) {
        int4 A  = __ldg(&adj4[e >> 2]);
        int4 Bv = __ldg(&adj4[(e >> 2) + 1]);
        uint4 t0 = T4[(size_t)A.x  * 32 + lane];
        uint4 t1 = T4[(size_t)A.y  * 32 + lane];
        uint4 t2 = T4[(size_t)A.z  * 32 + lane];
        uint4 t3 = T4[(size_t)A.w  * 32 + lane];
        uint4 t4 = T4[(size_t)Bv.x * 32 + lane];
        uint4 t5 = T4[(size_t)Bv.y * 32 + lane];
        uint4 t6 = T4[(size_t)Bv.z * 32 + lane];
        uint4 t7 = T4[(size_t)Bv.w * 32 + lane];
        acc8_fp16(acc, t0);
        acc8_fp16(acc, t1);
        acc8_fp16(acc, t2);
        acc8_fp16(acc, t3);
        acc8_fp16(acc, t4);
        acc8_fp16(acc, t5);
        acc8_fp16(acc, t6);
        acc8_fp16(acc, t7);
    }

    // exchange halves: lanes<16 hold sum(EL), lanes>=16 hold sum(ELS)
    float other[8];
#pragma unroll
    for (int k = 0; k < 8; k++)
        other[k] = __shfl_xor_sync(0xffffffffu, acc[k], 16);

    int sub = lane & 15;                      // channel group: c = sub*8 .. +7
    size_t rowf4 = (size_t)gw * 32 + sub * 2; // float4 index into [M_TOTAL, CC]
    float4 ea0 = ((const float4*)g_EA)[rowf4];
    float4 ea1 = ((const float4*)g_EA)[rowf4 + 1];
    float ea[8] = {ea0.x, ea0.y, ea0.z, ea0.w, ea1.x, ea1.y, ea1.z, ea1.w};

    float sE[8], sS[8];
    if (lane < 16) {
#pragma unroll
        for (int k = 0; k < 8; k++) { sE[k] = acc[k]; sS[k] = other[k]; }
    } else {
#pragma unroll
        for (int k = 0; k < 8; k++) { sE[k] = other[k]; sS[k] = acc[k]; }
    }

    float inv[8];
#pragma unroll
    for (int k = 0; k < 8; k++) inv[k] = 1.f / (1.f + ea[k] * sE[k]);

    if (lane < 16) {
        // write G = ea * sS * inv
        float4 G0, G1;
        G0.x = ea[0] * sS[0] * inv[0]; G0.y = ea[1] * sS[1] * inv[1];
        G0.z = ea[2] * sS[2] * inv[2]; G0.w = ea[3] * sS[3] * inv[3];
        G1.x = ea[4] * sS[4] * inv[4]; G1.y = ea[5] * sS[5] * inv[5];
        G1.z = ea[6] * sS[6] * inv[6]; G1.w = ea[7] * sS[7] * inv[7];
        ((float4*)g_G)[rowf4]     = G0;
        ((float4*)g_G)[rowf4 + 1] = G1;
    } else {
        // write SS = states * inv
        float4 st0 = ((const float4*)states)[rowf4];
        float4 st1 = ((const float4*)states)[rowf4 + 1];
        float4 S0, S1;
        S0.x = st0.x * inv[0]; S0.y = st0.y * inv[1];
        S0.z = st0.z * inv[2]; S0.w = st0.w * inv[3];
        S1.x = st1.x * inv[4]; S1.y = st1.y * inv[5];
        S1.z = st1.z * inv[6]; S1.w = st1.w * inv[7];
        ((float4*)g_SS)[rowf4]     = S0;
        ((float4*)g_SS)[rowf4 + 1] = S1;
    }
}

// ---------------- launch ----------------------------------------------------
extern "C" void kernel_launch(void* const* d_in, const int* in_sizes, int n_in,
                              void* d_out, int out_size) {
    const float* objects = (const float*)d_in[0];
    const float* Wos     = (const float*)d_in[1];
    const float* Wsa     = (const float*)d_in[2];
    const float* Wla     = (const float*)d_in[3];
    const float* att_b   = (const float*)d_in[4];
    const float* Wl      = (const float*)d_in[5];
    const float* st_b    = (const float*)d_in[6];
    const int*   conn    = (const int*)d_in[7];
    float* states = (float*)d_out;            // live states buffer, [B,N,C]

    cudaFuncSetAttribute(gemm_k<0>, cudaFuncAttributeMaxDynamicSharedMemorySize, GEMM_SMEM_BYTES);
    cudaFuncSetAttribute(gemm_k<1>, cudaFuncAttributeMaxDynamicSharedMemorySize, GEMM_SMEM_BYTES);
    cudaFuncSetAttribute(gemm_k<2>, cudaFuncAttributeMaxDynamicSharedMemorySize, GEMM_SMEM_BYTES);
    cudaFuncSetAttribute(gemm_k<3>, cudaFuncAttributeMaxDynamicSharedMemorySize, GEMM_SMEM_BYTES);

    float *pEA, *pG, *pSS;
    __half* pT;
    cudaGetSymbolAddress((void**)&pEA, g_EA);
    cudaGetSymbolAddress((void**)&pT,  g_T);
    cudaGetSymbolAddress((void**)&pG,  g_G);
    cudaGetSymbolAddress((void**)&pSS, g_SS);

    const int EDGE_BLOCKS = (BB * EE + 255) / 256;      // 2500
    const int GEMM_GRID   = M_TOTAL / TM;               // 625
    const int AGG_GRID    = (M_TOTAL * 32 + 255) / 256; // 5000
    const int INIT_GRID   = (BB * PADJ + 255) / 256;    // 6250

    // CSR build (per launch; connections are an input)
    init_kernel<<<INIT_GRID, 256>>>();
    count_kernel<<<EDGE_BLOCKS, 256>>>(conn);
    scan_kernel<<<BB, 1024>>>();
    fill_kernel<<<EDGE_BLOCKS, 256>>>(conn);

    // init states = tanh(objects @ Wos + st_b)
    gemm_k<0><<<GEMM_GRID, GEMM_THREADS, GEMM_SMEM_BYTES>>>(objects, Wos, st_b, nullptr, states, nullptr);

    for (int it = 0; it < ITERS; it++) {
        gemm_k<1><<<GEMM_GRID, GEMM_THREADS, GEMM_SMEM_BYTES>>>(states, Wsa, att_b, nullptr, pEA, nullptr);
        gemm_k<2><<<GEMM_GRID, GEMM_THREADS, GEMM_SMEM_BYTES>>>(states, Wla, nullptr, nullptr, nullptr, pT);
        agg_kernel<<<AGG_GRID, 256>>>(states);
        gemm_k<3><<<GEMM_GRID, GEMM_THREADS, GEMM_SMEM_BYTES>>>(pG, Wl, st_b, pSS, states, nullptr);
    }
}

// round 9
// speedup vs baseline: 2.0689x; 1.6141x over previous
#include <cuda_runtime.h>
#include <cuda_fp16.h>
#include <math.h>

#define BB 4
#define NN 10000
#define EE 160000
#define CC 128
#define ITERS 3
#define M_TOTAL (BB * NN)          // 40000 rows, = 625 * 64 exactly
#define TM 64
#define LDH 136                    // padded smem stride in halves (272B)
#define GEMM_THREADS 256
#define GEMM_SMEM_BYTES ((TM + CC) * LDH * 2)   // fp16 A tile + W = 52224 B

// ---------------- scratch (static device globals; no runtime allocation) ----
__device__ __align__(16) float g_EA [M_TOTAL * CC];      // exp(states@Wsa + att_b)
__device__ __align__(16) __half g_T[M_TOTAL * 2 * CC];   // per node: [EL(128) | ELS(128)] fp16
__device__ __align__(16) float g_G  [M_TOTAL * CC];      // linked_gated
__device__ __align__(16) float g_SS [M_TOTAL * CC];      // states / norm
__device__ int g_deg[M_TOTAL];
__device__ int g_cur[M_TOTAL];
__device__ int g_off[BB * (NN + 1)];
__device__ int g_adj[BB * 2 * EE];

// ---------------- CSR build ------------------------------------------------
__global__ void zero_deg_kernel() {
    int i = blockIdx.x * blockDim.x + threadIdx.x;
    if (i < M_TOTAL) g_deg[i] = 0;
}

__global__ void count_kernel(const int* __restrict__ conn) {
    int idx = blockIdx.x * blockDim.x + threadIdx.x;
    if (idx >= BB * EE) return;
    int b = idx / EE;
    int2 uv = ((const int2*)conn)[idx];
    atomicAdd(&g_deg[b * NN + uv.x], 1);
    atomicAdd(&g_deg[b * NN + uv.y], 1);
}

// one block (1024 threads) per batch: exclusive scan of degrees -> offsets
__global__ void scan_kernel() {
    const int CH = 10;                       // 1024*10 >= 10000
    int b = blockIdx.x;
    int t = threadIdx.x;
    int base = t * CH;
    int pref[CH];
    int s = 0;
#pragma unroll
    for (int i = 0; i < CH; i++) {
        int idx = base + i;
        int v = (idx < NN) ? g_deg[b * NN + idx] : 0;
        pref[i] = s;
        s += v;
    }
    int lane = t & 31, wid = t >> 5;
    int inc = s;
#pragma unroll
    for (int o = 1; o < 32; o <<= 1) {
        int n = __shfl_up_sync(0xffffffffu, inc, o);
        if (lane >= o) inc += n;
    }
    __shared__ int wtot[32];
    if (lane == 31) wtot[wid] = inc;
    __syncthreads();
    if (wid == 0) {
        int v = wtot[lane];
        int iv = v;
#pragma unroll
        for (int o = 1; o < 32; o <<= 1) {
            int n = __shfl_up_sync(0xffffffffu, iv, o);
            if (lane >= o) iv += n;
        }
        wtot[lane] = iv - v;                  // warp-exclusive offset
    }
    __syncthreads();
    int texcl = wtot[wid] + (inc - s);        // thread-exclusive offset
#pragma unroll
    for (int i = 0; i < CH; i++) {
        int idx = base + i;
        if (idx < NN) {
            int o = texcl + pref[i];
            g_off[b * (NN + 1) + idx] = o;
            g_cur[b * NN + idx] = o;
        }
    }
    if (t == blockDim.x - 1) g_off[b * (NN + 1) + NN] = texcl + s;
}

__global__ void fill_kernel(const int* __restrict__ conn) {
    int idx = blockIdx.x * blockDim.x + threadIdx.x;
    if (idx >= BB * EE) return;
    int b = idx / EE;
    int2 uv = ((const int2*)conn)[idx];
    int p = atomicAdd(&g_cur[b * NN + uv.x], 1);
    g_adj[b * 2 * EE + p] = uv.y;
    int q = atomicAdd(&g_cur[b * NN + uv.y], 1);
    g_adj[b * 2 * EE + q] = uv.x;
}

// ---------------- GEMM [40000,128] x [128,128] via mma.sync fp16 -----------
// A tile (TM x 128) and W (128 x 128) converted to fp16 in smem (stride LDH).
// 8 warps: warp_m = wid&3 (16 rows each), warp_n = wid>>2 (64 cols each).
// MODE 0: O1 = tanh(acc + bias)       MODE 1: O1 = exp(acc + bias)
// MODE 2: T[row] = { fp16(exp(acc)), fp16(exp(acc)*state) }
// MODE 3: O1 = tanh(acc + add + bias)
__device__ __forceinline__ unsigned smem_u32(const void* p) {
    return (unsigned)__cvta_generic_to_shared(p);
}

template <int MODE>
__global__ void gemm_k(const float* __restrict__ X, const float* __restrict__ W,
                       const float* __restrict__ bias, const float* __restrict__ add,
                       float* __restrict__ O1, __half* __restrict__ OT) {
    extern __shared__ __half sh[];
    __half* As  = sh;                 // TM x LDH
    __half* Wsh = sh + TM * LDH;      // CC x LDH
    int t = threadIdx.x;
    int block_row = blockIdx.x * TM;

    // load & convert W: 16384 floats = 4096 float4, 16 per thread
    const float4* W4 = (const float4*)W;
#pragma unroll
    for (int i = 0; i < 16; i++) {
        float4 v = W4[t + 256 * i];
        int e = (t + 256 * i) * 4;
        int r = e >> 7, c = e & 127;
        __half2* dst = (__half2*)&Wsh[r * LDH + c];
        dst[0] = __floats2half2_rn(v.x, v.y);
        dst[1] = __floats2half2_rn(v.z, v.w);
    }
    // load & convert X tile: 8192 floats = 2048 float4, 8 per thread
    const float4* X4 = (const float4*)(X + (size_t)block_row * CC);
#pragma unroll
    for (int i = 0; i < 8; i++) {
        float4 v = X4[t + 256 * i];
        int e = (t + 256 * i) * 4;
        int r = e >> 7, c = e & 127;
        __half2* dst = (__half2*)&As[r * LDH + c];
        dst[0] = __floats2half2_rn(v.x, v.y);
        dst[1] = __floats2half2_rn(v.z, v.w);
    }
    __syncthreads();

    int lane = t & 31, wid = t >> 5;
    int wm = (wid & 3) * 16;          // warp row base within tile
    int wn = (wid >> 2) * 64;         // warp col base

    float acc[8][4];
#pragma unroll
    for (int nf = 0; nf < 8; nf++)
#pragma unroll
        for (int q = 0; q < 4; q++) acc[nf][q] = 0.f;

    // A ldmatrix address pattern: t0-15 -> rows m0..15 @ k, t16-31 -> same rows @ k+8
    int a_row = wm + (lane & 15);
    int a_koff = (lane >> 4) << 3;
    // B ldmatrix.trans: t0-7 k0-7 @ n, t8-15 k8-15 @ n, t16-23 k0-7 @ n+8, t24-31 k8-15 @ n+8
    int b_krow = ((lane >> 3) & 1) * 8 + (lane & 7);
    int b_noff = (lane >> 4) << 3;

#pragma unroll
    for (int ks = 0; ks < 8; ks++) {
        int kk = ks * 16;
        unsigned a0, a1, a2, a3;
        unsigned aaddr = smem_u32(&As[a_row * LDH + kk + a_koff]);
        asm volatile("ldmatrix.sync.aligned.m8n8.x4.shared.b16 {%0,%1,%2,%3}, [%4];"
                     : "=r"(a0), "=r"(a1), "=r"(a2), "=r"(a3) : "r"(aaddr));
#pragma unroll
        for (int nf = 0; nf < 8; nf += 2) {
            unsigned b0, b1, b2, b3;
            unsigned baddr = smem_u32(&Wsh[(kk + b_krow) * LDH + wn + nf * 8 + b_noff]);
            asm volatile("ldmatrix.sync.aligned.m8n8.x4.trans.shared.b16 {%0,%1,%2,%3}, [%4];"
                         : "=r"(b0), "=r"(b1), "=r"(b2), "=r"(b3) : "r"(baddr));
            asm volatile("mma.sync.aligned.m16n8k16.row.col.f32.f16.f16.f32 "
                         "{%0,%1,%2,%3}, {%4,%5,%6,%7}, {%8,%9}, {%0,%1,%2,%3};"
                         : "+f"(acc[nf][0]), "+f"(acc[nf][1]), "+f"(acc[nf][2]), "+f"(acc[nf][3])
                         : "r"(a0), "r"(a1), "r"(a2), "r"(a3), "r"(b0), "r"(b1));
            asm volatile("mma.sync.aligned.m16n8k16.row.col.f32.f16.f16.f32 "
                         "{%0,%1,%2,%3}, {%4,%5,%6,%7}, {%8,%9}, {%0,%1,%2,%3};"
                         : "+f"(acc[nf+1][0]), "+f"(acc[nf+1][1]), "+f"(acc[nf+1][2]), "+f"(acc[nf+1][3])
                         : "r"(a0), "r"(a1), "r"(a2), "r"(a3), "r"(b2), "r"(b3));
        }
    }

    // epilogue: thread holds (r0,c),(r0,c+1),(r1,c),(r1,c+1) per nfrag
    int lr0 = wm + (lane >> 2);
    int col_in = (lane & 3) * 2;
#pragma unroll
    for (int nf = 0; nf < 8; nf++) {
        int col = wn + nf * 8 + col_in;
#pragma unroll
        for (int half = 0; half < 2; half++) {
            int lrow = lr0 + half * 8;
            size_t grow = (size_t)(block_row + lrow);
            float v0 = acc[nf][half * 2 + 0];
            float v1 = acc[nf][half * 2 + 1];
            if (MODE == 0 || MODE == 1 || MODE == 3) {
                float2 bz = *(const float2*)&bias[col];
                if (MODE == 3) {
                    float2 ad = *(const float2*)&add[grow * CC + col];
                    v0 += ad.x; v1 += ad.y;
                }
                float2 o;
                if (MODE == 1) { o.x = __expf(v0 + bz.x); o.y = __expf(v1 + bz.y); }
                else           { o.x = tanhf(v0 + bz.x);  o.y = tanhf(v1 + bz.y); }
                *(float2*)&O1[grow * CC + col] = o;
            } else {  // MODE 2
                float el0 = __expf(v0), el1 = __expf(v1);
                float s0 = __half2float(As[lrow * LDH + col]);
                float s1 = __half2float(As[lrow * LDH + col + 1]);
                __half2 e  = __floats2half2_rn(el0, el1);
                __half2 es = __floats2half2_rn(el0 * s0, el1 * s1);
                *(__half2*)&OT[grow * 2 * CC + col]      = e;
                *(__half2*)&OT[grow * 2 * CC + CC + col] = es;
            }
        }
    }
}

// ---------------- per-node aggregation (one warp per node, no atomics) -----
// Combined fp16 table: one LDG.128 per edge per warp fetches EL|ELS (512B).
// Lanes 0-15 accumulate EL channels (8 each), lanes 16-31 accumulate ELS.
__device__ __forceinline__ void acc8_fp16(float* acc, uint4 v) {
    unsigned int u[4] = {v.x, v.y, v.z, v.w};
#pragma unroll
    for (int q = 0; q < 4; q++) {
        float2 f = __half22float2(*(__half2*)&u[q]);
        acc[2 * q]     += f.x;
        acc[2 * q + 1] += f.y;
    }
}

__global__ void agg_kernel(const float* __restrict__ states) {
    int gw = (blockIdx.x * blockDim.x + threadIdx.x) >> 5;
    int lane = threadIdx.x & 31;
    if (gw >= M_TOTAL) return;
    int b = gw / NN;
    int i = gw - b * NN;

    int e  = g_off[b * (NN + 1) + i];
    int e2 = g_off[b * (NN + 1) + i + 1];
    const int* __restrict__ adj = g_adj + (size_t)b * 2 * EE;
    const uint4* __restrict__ T4 = (const uint4*)(g_T + (size_t)b * NN * 2 * CC);

    float acc[8];
#pragma unroll
    for (int k = 0; k < 8; k++) acc[k] = 0.f;

    for (; e + 4 <= e2; e += 4) {
        int j0 = __ldg(adj + e);
        int j1 = __ldg(adj + e + 1);
        int j2 = __ldg(adj + e + 2);
        int j3 = __ldg(adj + e + 3);
        uint4 t0 = T4[(size_t)j0 * 32 + lane];
        uint4 t1 = T4[(size_t)j1 * 32 + lane];
        uint4 t2 = T4[(size_t)j2 * 32 + lane];
        uint4 t3 = T4[(size_t)j3 * 32 + lane];
        acc8_fp16(acc, t0);
        acc8_fp16(acc, t1);
        acc8_fp16(acc, t2);
        acc8_fp16(acc, t3);
    }
    for (; e < e2; e++) {
        int j = __ldg(adj + e);
        uint4 t = T4[(size_t)j * 32 + lane];
        acc8_fp16(acc, t);
    }

    // exchange halves: lanes<16 hold sum(EL), lanes>=16 hold sum(ELS)
    float other[8];
#pragma unroll
    for (int k = 0; k < 8; k++)
        other[k] = __shfl_xor_sync(0xffffffffu, acc[k], 16);

    int sub = lane & 15;                      // channel group: c = sub*8 .. +7
    size_t rowf4 = (size_t)gw * 32 + sub * 2; // float4 index into [M_TOTAL, CC]
    float4 ea0 = ((const float4*)g_EA)[rowf4];
    float4 ea1 = ((const float4*)g_EA)[rowf4 + 1];
    float ea[8] = {ea0.x, ea0.y, ea0.z, ea0.w, ea1.x, ea1.y, ea1.z, ea1.w};

    float sE[8], sS[8];
    if (lane < 16) {
#pragma unroll
        for (int k = 0; k < 8; k++) { sE[k] = acc[k]; sS[k] = other[k]; }
    } else {
#pragma unroll
        for (int k = 0; k < 8; k++) { sE[k] = other[k]; sS[k] = acc[k]; }
    }

    float inv[8];
#pragma unroll
    for (int k = 0; k < 8; k++) inv[k] = 1.f / (1.f + ea[k] * sE[k]);

    if (lane < 16) {
        // write G = ea * sS * inv
        float4 G0, G1;
        G0.x = ea[0] * sS[0] * inv[0]; G0.y = ea[1] * sS[1] * inv[1];
        G0.z = ea[2] * sS[2] * inv[2]; G0.w = ea[3] * sS[3] * inv[3];
        G1.x = ea[4] * sS[4] * inv[4]; G1.y = ea[5] * sS[5] * inv[5];
        G1.z = ea[6] * sS[6] * inv[6]; G1.w = ea[7] * sS[7] * inv[7];
        ((float4*)g_G)[rowf4]     = G0;
        ((float4*)g_G)[rowf4 + 1] = G1;
    } else {
        // write SS = states * inv
        float4 st0 = ((const float4*)states)[rowf4];
        float4 st1 = ((const float4*)states)[rowf4 + 1];
        float4 S0, S1;
        S0.x = st0.x * inv[0]; S0.y = st0.y * inv[1];
        S0.z = st0.z * inv[2]; S0.w = st0.w * inv[3];
        S1.x = st1.x * inv[4]; S1.y = st1.y * inv[5];
        S1.z = st1.z * inv[6]; S1.w = st1.w * inv[7];
        ((float4*)g_SS)[rowf4]     = S0;
        ((float4*)g_SS)[rowf4 + 1] = S1;
    }
}

// ---------------- launch ----------------------------------------------------
extern "C" void kernel_launch(void* const* d_in, const int* in_sizes, int n_in,
                              void* d_out, int out_size) {
    const float* objects = (const float*)d_in[0];
    const float* Wos     = (const float*)d_in[1];
    const float* Wsa     = (const float*)d_in[2];
    const float* Wla     = (const float*)d_in[3];
    const float* att_b   = (const float*)d_in[4];
    const float* Wl      = (const float*)d_in[5];
    const float* st_b    = (const float*)d_in[6];
    const int*   conn    = (const int*)d_in[7];
    float* states = (float*)d_out;            // live states buffer, [B,N,C]

    cudaFuncSetAttribute(gemm_k<0>, cudaFuncAttributeMaxDynamicSharedMemorySize, GEMM_SMEM_BYTES);
    cudaFuncSetAttribute(gemm_k<1>, cudaFuncAttributeMaxDynamicSharedMemorySize, GEMM_SMEM_BYTES);
    cudaFuncSetAttribute(gemm_k<2>, cudaFuncAttributeMaxDynamicSharedMemorySize, GEMM_SMEM_BYTES);
    cudaFuncSetAttribute(gemm_k<3>, cudaFuncAttributeMaxDynamicSharedMemorySize, GEMM_SMEM_BYTES);

    float *pEA, *pG, *pSS;
    __half* pT;
    cudaGetSymbolAddress((void**)&pEA, g_EA);
    cudaGetSymbolAddress((void**)&pT,  g_T);
    cudaGetSymbolAddress((void**)&pG,  g_G);
    cudaGetSymbolAddress((void**)&pSS, g_SS);

    const int EDGE_BLOCKS = (BB * EE + 255) / 256;      // 2500
    const int GEMM_GRID   = M_TOTAL / TM;               // 625
    const int AGG_GRID    = (M_TOTAL * 32 + 255) / 256; // 5000

    // CSR build (per launch; connections are an input)
    zero_deg_kernel<<<(M_TOTAL + 255) / 256, 256>>>();
    count_kernel<<<EDGE_BLOCKS, 256>>>(conn);
    scan_kernel<<<BB, 1024>>>();
    fill_kernel<<<EDGE_BLOCKS, 256>>>(conn);

    // init states = tanh(objects @ Wos + st_b)
    gemm_k<0><<<GEMM_GRID, GEMM_THREADS, GEMM_SMEM_BYTES>>>(objects, Wos, st_b, nullptr, states, nullptr);

    for (int it = 0; it < ITERS; it++) {
        gemm_k<1><<<GEMM_GRID, GEMM_THREADS, GEMM_SMEM_BYTES>>>(states, Wsa, att_b, nullptr, pEA, nullptr);
        gemm_k<2><<<GEMM_GRID, GEMM_THREADS, GEMM_SMEM_BYTES>>>(states, Wla, nullptr, nullptr, nullptr, pT);
        agg_kernel<<<AGG_GRID, 256>>>(states);
        gemm_k<3><<<GEMM_GRID, GEMM_THREADS, GEMM_SMEM_BYTES>>>(pG, Wl, st_b, pSS, states, nullptr);
    }
}

// round 10
// speedup vs baseline: 2.1941x; 1.0605x over previous
#include <cuda_runtime.h>
#include <cuda_fp16.h>
#include <math.h>

#define BB 4
#define NN 10000
#define EE 160000
#define CC 128
#define ITERS 3
#define M_TOTAL (BB * NN)          // 40000 rows, = 625 * 64 exactly
#define TM 64
#define LDH 136                    // padded smem stride in halves (272B)
#define GEMM_THREADS 256
#define GEMM_SMEM_BYTES ((TM + CC) * LDH * 2)        // 52224 B
#define GEMM12_SMEM_BYTES ((TM + 2 * CC) * LDH * 2)  // 87040 B
#define STRIDE 128                 // ELL slots per node (mean degree 32)

// ---------------- scratch (static device globals; no runtime allocation) ----
__device__ __align__(16) float g_EA [M_TOTAL * CC];      // exp(states@Wsa + att_b)
__device__ __align__(16) __half g_T[M_TOTAL * 2 * CC];   // per node: [EL(128) | ELS(128)] fp16
__device__ __align__(16) float g_G  [M_TOTAL * CC];      // linked_gated
__device__ __align__(16) float g_SS [M_TOTAL * CC];      // states / norm
__device__ int g_cur[M_TOTAL];                           // fill cursor == degree after fill
__device__ int g_adj[M_TOTAL * STRIDE];                  // ELL adjacency

// ---------------- ELL build ------------------------------------------------
__global__ void zero_cur_kernel() {
    int i = blockIdx.x * blockDim.x + threadIdx.x;
    if (i < M_TOTAL) g_cur[i] = 0;
}

__global__ void fill_kernel(const int* __restrict__ conn) {
    int idx = blockIdx.x * blockDim.x + threadIdx.x;
    if (idx >= BB * EE) return;
    int b = idx / EE;
    int2 uv = ((const int2*)conn)[idx];
    int nu = b * NN + uv.x, nv = b * NN + uv.y;
    int p = atomicAdd(&g_cur[nu], 1);
    if (p < STRIDE) g_adj[(size_t)nu * STRIDE + p] = uv.y;
    int q = atomicAdd(&g_cur[nv], 1);
    if (q < STRIDE) g_adj[(size_t)nv * STRIDE + q] = uv.x;
}

// ---------------- mma.sync helpers -----------------------------------------
__device__ __forceinline__ unsigned smem_u32(const void* p) {
    return (unsigned)__cvta_generic_to_shared(p);
}

#define LDSM_X4(r0, r1, r2, r3, addr) \
    asm volatile("ldmatrix.sync.aligned.m8n8.x4.shared.b16 {%0,%1,%2,%3}, [%4];" \
                 : "=r"(r0), "=r"(r1), "=r"(r2), "=r"(r3) : "r"(addr))
#define LDSM_X4T(r0, r1, r2, r3, addr) \
    asm volatile("ldmatrix.sync.aligned.m8n8.x4.trans.shared.b16 {%0,%1,%2,%3}, [%4];" \
                 : "=r"(r0), "=r"(r1), "=r"(r2), "=r"(r3) : "r"(addr))
#define MMA16816(acc, a0, a1, a2, a3, b0, b1) \
    asm volatile("mma.sync.aligned.m16n8k16.row.col.f32.f16.f16.f32 " \
                 "{%0,%1,%2,%3}, {%4,%5,%6,%7}, {%8,%9}, {%0,%1,%2,%3};" \
                 : "+f"(acc[0]), "+f"(acc[1]), "+f"(acc[2]), "+f"(acc[3]) \
                 : "r"(a0), "r"(a1), "r"(a2), "r"(a3), "r"(b0), "r"(b1))

// ---------------- GEMM [40000,128] x [128,128] via mma.sync fp16 -----------
// 8 warps: warp_m = wid&3 (16 rows), warp_n = wid>>2 (64 cols).
// MODE 0: O1 = tanh(acc + bias)       MODE 3: O1 = tanh(acc + add + bias)
template <int MODE>
__global__ void gemm_k(const float* __restrict__ X, const float* __restrict__ W,
                       const float* __restrict__ bias, const float* __restrict__ add,
                       float* __restrict__ O1) {
    extern __shared__ __half sh[];
    __half* As  = sh;                 // TM x LDH
    __half* Wsh = sh + TM * LDH;      // CC x LDH
    int t = threadIdx.x;
    int block_row = blockIdx.x * TM;

    const float4* W4 = (const float4*)W;
#pragma unroll
    for (int i = 0; i < 16; i++) {
        float4 v = W4[t + 256 * i];
        int e = (t + 256 * i) * 4;
        int r = e >> 7, c = e & 127;
        __half2* dst = (__half2*)&Wsh[r * LDH + c];
        dst[0] = __floats2half2_rn(v.x, v.y);
        dst[1] = __floats2half2_rn(v.z, v.w);
    }
    const float4* X4 = (const float4*)(X + (size_t)block_row * CC);
#pragma unroll
    for (int i = 0; i < 8; i++) {
        float4 v = X4[t + 256 * i];
        int e = (t + 256 * i) * 4;
        int r = e >> 7, c = e & 127;
        __half2* dst = (__half2*)&As[r * LDH + c];
        dst[0] = __floats2half2_rn(v.x, v.y);
        dst[1] = __floats2half2_rn(v.z, v.w);
    }
    __syncthreads();

    int lane = t & 31, wid = t >> 5;
    int wm = (wid & 3) * 16;
    int wn = (wid >> 2) * 64;

    float acc[8][4];
#pragma unroll
    for (int nf = 0; nf < 8; nf++)
#pragma unroll
        for (int q = 0; q < 4; q++) acc[nf][q] = 0.f;

    int a_row = wm + (lane & 15);
    int a_koff = (lane >> 4) << 3;
    int b_krow = ((lane >> 3) & 1) * 8 + (lane & 7);
    int b_noff = (lane >> 4) << 3;

#pragma unroll
    for (int ks = 0; ks < 8; ks++) {
        int kk = ks * 16;
        unsigned a0, a1, a2, a3;
        LDSM_X4(a0, a1, a2, a3, smem_u32(&As[a_row * LDH + kk + a_koff]));
#pragma unroll
        for (int nf = 0; nf < 8; nf += 2) {
            unsigned b0, b1, b2, b3;
            LDSM_X4T(b0, b1, b2, b3, smem_u32(&Wsh[(kk + b_krow) * LDH + wn + nf * 8 + b_noff]));
            MMA16816(acc[nf],     a0, a1, a2, a3, b0, b1);
            MMA16816(acc[nf + 1], a0, a1, a2, a3, b2, b3);
        }
    }

    int lr0 = wm + (lane >> 2);
    int col_in = (lane & 3) * 2;
#pragma unroll
    for (int nf = 0; nf < 8; nf++) {
        int col = wn + nf * 8 + col_in;
#pragma unroll
        for (int half = 0; half < 2; half++) {
            int lrow = lr0 + half * 8;
            size_t grow = (size_t)(block_row + lrow);
            float v0 = acc[nf][half * 2 + 0];
            float v1 = acc[nf][half * 2 + 1];
            float2 bz = *(const float2*)&bias[col];
            if (MODE == 3) {
                float2 ad = *(const float2*)&add[grow * CC + col];
                v0 += ad.x; v1 += ad.y;
            }
            float2 o;
            o.x = tanhf(v0 + bz.x);
            o.y = tanhf(v1 + bz.y);
            *(float2*)&O1[grow * CC + col] = o;
        }
    }
}

// ---------------- fused EA + EL/ELS GEMM (one X tile, two W matrices) ------
__global__ void gemm12_k(const float* __restrict__ X,
                         const float* __restrict__ W1,   // state_attention_W -> EA
                         const float* __restrict__ W2,   // linked_state_attention_W -> EL
                         const float* __restrict__ attb,
                         float* __restrict__ OEA, __half* __restrict__ OT) {
    extern __shared__ __half sh[];
    __half* As  = sh;                      // TM x LDH
    __half* W1s = sh + TM * LDH;           // CC x LDH
    __half* W2s = sh + (TM + CC) * LDH;    // CC x LDH
    int t = threadIdx.x;
    int block_row = blockIdx.x * TM;

    const float4* W14 = (const float4*)W1;
    const float4* W24 = (const float4*)W2;
#pragma unroll
    for (int i = 0; i < 16; i++) {
        float4 v = W14[t + 256 * i];
        int e = (t + 256 * i) * 4;
        int r = e >> 7, c = e & 127;
        __half2* dst = (__half2*)&W1s[r * LDH + c];
        dst[0] = __floats2half2_rn(v.x, v.y);
        dst[1] = __floats2half2_rn(v.z, v.w);
        float4 u = W24[t + 256 * i];
        __half2* dst2 = (__half2*)&W2s[r * LDH + c];
        dst2[0] = __floats2half2_rn(u.x, u.y);
        dst2[1] = __floats2half2_rn(u.z, u.w);
    }
    const float4* X4 = (const float4*)(X + (size_t)block_row * CC);
#pragma unroll
    for (int i = 0; i < 8; i++) {
        float4 v = X4[t + 256 * i];
        int e = (t + 256 * i) * 4;
        int r = e >> 7, c = e & 127;
        __half2* dst = (__half2*)&As[r * LDH + c];
        dst[0] = __floats2half2_rn(v.x, v.y);
        dst[1] = __floats2half2_rn(v.z, v.w);
    }
    __syncthreads();

    int lane = t & 31, wid = t >> 5;
    int wm = (wid & 3) * 16;
    int wn = (wid >> 2) * 64;

    float accE[8][4], accL[8][4];
#pragma unroll
    for (int nf = 0; nf < 8; nf++)
#pragma unroll
        for (int q = 0; q < 4; q++) { accE[nf][q] = 0.f; accL[nf][q] = 0.f; }

    int a_row = wm + (lane & 15);
    int a_koff = (lane >> 4) << 3;
    int b_krow = ((lane >> 3) & 1) * 8 + (lane & 7);
    int b_noff = (lane >> 4) << 3;

#pragma unroll
    for (int ks = 0; ks < 8; ks++) {
        int kk = ks * 16;
        unsigned a0, a1, a2, a3;
        LDSM_X4(a0, a1, a2, a3, smem_u32(&As[a_row * LDH + kk + a_koff]));
#pragma unroll
        for (int nf = 0; nf < 8; nf += 2) {
            unsigned b0, b1, b2, b3;
            LDSM_X4T(b0, b1, b2, b3, smem_u32(&W1s[(kk + b_krow) * LDH + wn + nf * 8 + b_noff]));
            MMA16816(accE[nf],     a0, a1, a2, a3, b0, b1);
            MMA16816(accE[nf + 1], a0, a1, a2, a3, b2, b3);
            LDSM_X4T(b0, b1, b2, b3, smem_u32(&W2s[(kk + b_krow) * LDH + wn + nf * 8 + b_noff]));
            MMA16816(accL[nf],     a0, a1, a2, a3, b0, b1);
            MMA16816(accL[nf + 1], a0, a1, a2, a3, b2, b3);
        }
    }

    int lr0 = wm + (lane >> 2);
    int col_in = (lane & 3) * 2;
#pragma unroll
    for (int nf = 0; nf < 8; nf++) {
        int col = wn + nf * 8 + col_in;
#pragma unroll
        for (int half = 0; half < 2; half++) {
            int lrow = lr0 + half * 8;
            size_t grow = (size_t)(block_row + lrow);
            // EA
            float2 bz = *(const float2*)&attb[col];
            float2 oe;
            oe.x = __expf(accE[nf][half * 2 + 0] + bz.x);
            oe.y = __expf(accE[nf][half * 2 + 1] + bz.y);
            *(float2*)&OEA[grow * CC + col] = oe;
            // EL / ELS
            float el0 = __expf(accL[nf][half * 2 + 0]);
            float el1 = __expf(accL[nf][half * 2 + 1]);
            float s0 = __half2float(As[lrow * LDH + col]);
            float s1 = __half2float(As[lrow * LDH + col + 1]);
            __half2 e  = __floats2half2_rn(el0, el1);
            __half2 es = __floats2half2_rn(el0 * s0, el1 * s1);
            *(__half2*)&OT[grow * 2 * CC + col]      = e;
            *(__half2*)&OT[grow * 2 * CC + CC + col] = es;
        }
    }
}

// ---------------- per-node aggregation (one warp per node, no atomics) -----
__device__ __forceinline__ void acc8_fp16(float* acc, uint4 v) {
    unsigned int u[4] = {v.x, v.y, v.z, v.w};
#pragma unroll
    for (int q = 0; q < 4; q++) {
        float2 f = __half22float2(*(__half2*)&u[q]);
        acc[2 * q]     += f.x;
        acc[2 * q + 1] += f.y;
    }
}

__global__ void agg_kernel(const float* __restrict__ states) {
    int gw = (blockIdx.x * blockDim.x + threadIdx.x) >> 5;
    int lane = threadIdx.x & 31;
    if (gw >= M_TOTAL) return;
    int b = gw / NN;

    int deg = g_cur[gw];
    if (deg > STRIDE) deg = STRIDE;
    const int* __restrict__ adj = g_adj + (size_t)gw * STRIDE;
    const uint4* __restrict__ T4 = (const uint4*)(g_T + (size_t)b * NN * 2 * CC);

    float acc[8];
#pragma unroll
    for (int k = 0; k < 8; k++) acc[k] = 0.f;

    int e = 0;
    for (; e + 4 <= deg; e += 4) {
        int j0 = __ldg(adj + e);
        int j1 = __ldg(adj + e + 1);
        int j2 = __ldg(adj + e + 2);
        int j3 = __ldg(adj + e + 3);
        uint4 t0 = T4[(size_t)j0 * 32 + lane];
        uint4 t1 = T4[(size_t)j1 * 32 + lane];
        uint4 t2 = T4[(size_t)j2 * 32 + lane];
        uint4 t3 = T4[(size_t)j3 * 32 + lane];
        acc8_fp16(acc, t0);
        acc8_fp16(acc, t1);
        acc8_fp16(acc, t2);
        acc8_fp16(acc, t3);
    }
    for (; e < deg; e++) {
        int j = __ldg(adj + e);
        uint4 tv = T4[(size_t)j * 32 + lane];
        acc8_fp16(acc, tv);
    }

    float other[8];
#pragma unroll
    for (int k = 0; k < 8; k++)
        other[k] = __shfl_xor_sync(0xffffffffu, acc[k], 16);

    int sub = lane & 15;
    size_t rowf4 = (size_t)gw * 32 + sub * 2;
    float4 ea0 = ((const float4*)g_EA)[rowf4];
    float4 ea1 = ((const float4*)g_EA)[rowf4 + 1];
    float ea[8] = {ea0.x, ea0.y, ea0.z, ea0.w, ea1.x, ea1.y, ea1.z, ea1.w};

    float sE[8], sS[8];
    if (lane < 16) {
#pragma unroll
        for (int k = 0; k < 8; k++) { sE[k] = acc[k]; sS[k] = other[k]; }
    } else {
#pragma unroll
        for (int k = 0; k < 8; k++) { sE[k] = other[k]; sS[k] = acc[k]; }
    }

    float inv[8];
#pragma unroll
    for (int k = 0; k < 8; k++) inv[k] = 1.f / (1.f + ea[k] * sE[k]);

    if (lane < 16) {
        float4 G0, G1;
        G0.x = ea[0] * sS[0] * inv[0]; G0.y = ea[1] * sS[1] * inv[1];
        G0.z = ea[2] * sS[2] * inv[2]; G0.w = ea[3] * sS[3] * inv[3];
        G1.x = ea[4] * sS[4] * inv[4]; G1.y = ea[5] * sS[5] * inv[5];
        G1.z = ea[6] * sS[6] * inv[6]; G1.w = ea[7] * sS[7] * inv[7];
        ((float4*)g_G)[rowf4]     = G0;
        ((float4*)g_G)[rowf4 + 1] = G1;
    } else {
        float4 st0 = ((const float4*)states)[rowf4];
        float4 st1 = ((const float4*)states)[rowf4 + 1];
        float4 S0, S1;
        S0.x = st0.x * inv[0]; S0.y = st0.y * inv[1];
        S0.z = st0.z * inv[2]; S0.w = st0.w * inv[3];
        S1.x = st1.x * inv[4]; S1.y = st1.y * inv[5];
        S1.z = st1.z * inv[6]; S1.w = st1.w * inv[7];
        ((float4*)g_SS)[rowf4]     = S0;
        ((float4*)g_SS)[rowf4 + 1] = S1;
    }
}

// ---------------- launch ----------------------------------------------------
extern "C" void kernel_launch(void* const* d_in, const int* in_sizes, int n_in,
                              void* d_out, int out_size) {
    const float* objects = (const float*)d_in[0];
    const float* Wos     = (const float*)d_in[1];
    const float* Wsa     = (const float*)d_in[2];
    const float* Wla     = (const float*)d_in[3];
    const float* att_b   = (const float*)d_in[4];
    const float* Wl      = (const float*)d_in[5];
    const float* st_b    = (const float*)d_in[6];
    const int*   conn    = (const int*)d_in[7];
    float* states = (float*)d_out;            // live states buffer, [B,N,C]

    cudaFuncSetAttribute(gemm_k<0>, cudaFuncAttributeMaxDynamicSharedMemorySize, GEMM_SMEM_BYTES);
    cudaFuncSetAttribute(gemm_k<3>, cudaFuncAttributeMaxDynamicSharedMemorySize, GEMM_SMEM_BYTES);
    cudaFuncSetAttribute(gemm12_k, cudaFuncAttributeMaxDynamicSharedMemorySize, GEMM12_SMEM_BYTES);

    float *pEA, *pG, *pSS;
    __half* pT;
    cudaGetSymbolAddress((void**)&pEA, g_EA);
    cudaGetSymbolAddress((void**)&pT,  g_T);
    cudaGetSymbolAddress((void**)&pG,  g_G);
    cudaGetSymbolAddress((void**)&pSS, g_SS);

    const int EDGE_BLOCKS = (BB * EE + 255) / 256;      // 2500
    const int GEMM_GRID   = M_TOTAL / TM;               // 625
    const int AGG_GRID    = (M_TOTAL * 32 + 255) / 256; // 5000

    // ELL build (per launch; connections are an input)
    zero_cur_kernel<<<(M_TOTAL + 255) / 256, 256>>>();
    fill_kernel<<<EDGE_BLOCKS, 256>>>(conn);

    // init states = tanh(objects @ Wos + st_b)
    gemm_k<0><<<GEMM_GRID, GEMM_THREADS, GEMM_SMEM_BYTES>>>(objects, Wos, st_b, nullptr, states);

    for (int it = 0; it < ITERS; it++) {
        gemm12_k<<<GEMM_GRID, GEMM_THREADS, GEMM12_SMEM_BYTES>>>(states, Wsa, Wla, att_b, pEA, pT);
        agg_kernel<<<AGG_GRID, 256>>>(states);
        gemm_k<3><<<GEMM_GRID, GEMM_THREADS, GEMM_SMEM_BYTES>>>(pG, Wl, st_b, pSS, states);
    }
}

// round 11
// speedup vs baseline: 2.2381x; 1.0200x over previous
#include <cuda_runtime.h>
#include <cuda_fp16.h>
#include <math.h>

#define BB 4
#define NN 10000
#define EE 160000
#define CC 128
#define ITERS 3
#define M_TOTAL (BB * NN)          // 40000 rows, = 625 * 64 exactly
#define TM 64
#define LDH 136                    // padded smem stride in halves (272B)
#define GEMM_THREADS 512
#define GEMM_SMEM_BYTES ((TM + CC) * LDH * 2)        // 52224 B
#define GEMM12_SMEM_BYTES ((TM + 2 * CC) * LDH * 2)  // 87040 B
#define STRIDE 128                 // ELL slots per node (mean degree 32)

// ---------------- scratch (static device globals; no runtime allocation) ----
__device__ __align__(16) float g_EA [M_TOTAL * CC];      // exp(states@Wsa + att_b)
__device__ __align__(16) __half g_T[M_TOTAL * 2 * CC];   // per node: [EL(128) | ELS(128)] fp16
__device__ __align__(16) float g_G  [M_TOTAL * CC];      // linked_gated
__device__ __align__(16) float g_SS [M_TOTAL * CC];      // states / norm
__device__ int g_cur[M_TOTAL];                           // fill cursor == degree after fill
__device__ int g_adj[M_TOTAL * STRIDE];                  // ELL adjacency

// ---------------- ELL build ------------------------------------------------
__global__ void zero_cur_kernel() {
    int i = blockIdx.x * blockDim.x + threadIdx.x;
    if (i < M_TOTAL) g_cur[i] = 0;
}

__global__ void fill_kernel(const int* __restrict__ conn) {
    int idx = blockIdx.x * blockDim.x + threadIdx.x;
    if (idx >= BB * EE) return;
    int b = idx / EE;
    int2 uv = ((const int2*)conn)[idx];
    int nu = b * NN + uv.x, nv = b * NN + uv.y;
    int p = atomicAdd(&g_cur[nu], 1);
    if (p < STRIDE) g_adj[(size_t)nu * STRIDE + p] = uv.y;
    int q = atomicAdd(&g_cur[nv], 1);
    if (q < STRIDE) g_adj[(size_t)nv * STRIDE + q] = uv.x;
}

// ---------------- mma.sync helpers -----------------------------------------
__device__ __forceinline__ unsigned smem_u32(const void* p) {
    return (unsigned)__cvta_generic_to_shared(p);
}

#define LDSM_X4(r0, r1, r2, r3, addr) \
    asm volatile("ldmatrix.sync.aligned.m8n8.x4.shared.b16 {%0,%1,%2,%3}, [%4];" \
                 : "=r"(r0), "=r"(r1), "=r"(r2), "=r"(r3) : "r"(addr))
#define LDSM_X4T(r0, r1, r2, r3, addr) \
    asm volatile("ldmatrix.sync.aligned.m8n8.x4.trans.shared.b16 {%0,%1,%2,%3}, [%4];" \
                 : "=r"(r0), "=r"(r1), "=r"(r2), "=r"(r3) : "r"(addr))
#define MMA16816(acc, a0, a1, a2, a3, b0, b1) \
    asm volatile("mma.sync.aligned.m16n8k16.row.col.f32.f16.f16.f32 " \
                 "{%0,%1,%2,%3}, {%4,%5,%6,%7}, {%8,%9}, {%0,%1,%2,%3};" \
                 : "+f"(acc[0]), "+f"(acc[1]), "+f"(acc[2]), "+f"(acc[3]) \
                 : "r"(a0), "r"(a1), "r"(a2), "r"(a3), "r"(b0), "r"(b1))

// ---------------- GEMM [40000,128] x [128,128] via mma.sync fp16 -----------
// 16 warps: warp_m = wid&3 (16 rows), warp_n = wid>>2 (32 cols).
// MODE 0: O1 = tanh(acc + bias)       MODE 3: O1 = tanh(acc + add + bias)
template <int MODE>
__global__ void __launch_bounds__(GEMM_THREADS, 2)
gemm_k(const float* __restrict__ X, const float* __restrict__ W,
       const float* __restrict__ bias, const float* __restrict__ add,
       float* __restrict__ O1) {
    extern __shared__ __half sh[];
    __half* As  = sh;                 // TM x LDH
    __half* Wsh = sh + TM * LDH;      // CC x LDH
    int t = threadIdx.x;
    int block_row = blockIdx.x * TM;

    // W: 4096 float4, 8 per thread
    const float4* W4 = (const float4*)W;
#pragma unroll
    for (int i = 0; i < 8; i++) {
        float4 v = W4[t + 512 * i];
        int e = (t + 512 * i) * 4;
        int r = e >> 7, c = e & 127;
        __half2* dst = (__half2*)&Wsh[r * LDH + c];
        dst[0] = __floats2half2_rn(v.x, v.y);
        dst[1] = __floats2half2_rn(v.z, v.w);
    }
    // X tile: 2048 float4, 4 per thread
    const float4* X4 = (const float4*)(X + (size_t)block_row * CC);
#pragma unroll
    for (int i = 0; i < 4; i++) {
        float4 v = X4[t + 512 * i];
        int e = (t + 512 * i) * 4;
        int r = e >> 7, c = e & 127;
        __half2* dst = (__half2*)&As[r * LDH + c];
        dst[0] = __floats2half2_rn(v.x, v.y);
        dst[1] = __floats2half2_rn(v.z, v.w);
    }
    __syncthreads();

    int lane = t & 31, wid = t >> 5;
    int wm = (wid & 3) * 16;
    int wn = (wid >> 2) * 32;

    float acc[4][4];
#pragma unroll
    for (int nf = 0; nf < 4; nf++)
#pragma unroll
        for (int q = 0; q < 4; q++) acc[nf][q] = 0.f;

    int a_row = wm + (lane & 15);
    int a_koff = (lane >> 4) << 3;
    int b_krow = ((lane >> 3) & 1) * 8 + (lane & 7);
    int b_noff = (lane >> 4) << 3;

#pragma unroll
    for (int ks = 0; ks < 8; ks++) {
        int kk = ks * 16;
        unsigned a0, a1, a2, a3;
        LDSM_X4(a0, a1, a2, a3, smem_u32(&As[a_row * LDH + kk + a_koff]));
#pragma unroll
        for (int nf = 0; nf < 4; nf += 2) {
            unsigned b0, b1, b2, b3;
            LDSM_X4T(b0, b1, b2, b3, smem_u32(&Wsh[(kk + b_krow) * LDH + wn + nf * 8 + b_noff]));
            MMA16816(acc[nf],     a0, a1, a2, a3, b0, b1);
            MMA16816(acc[nf + 1], a0, a1, a2, a3, b2, b3);
        }
    }

    int lr0 = wm + (lane >> 2);
    int col_in = (lane & 3) * 2;
#pragma unroll
    for (int nf = 0; nf < 4; nf++) {
        int col = wn + nf * 8 + col_in;
#pragma unroll
        for (int half = 0; half < 2; half++) {
            int lrow = lr0 + half * 8;
            size_t grow = (size_t)(block_row + lrow);
            float v0 = acc[nf][half * 2 + 0];
            float v1 = acc[nf][half * 2 + 1];
            float2 bz = *(const float2*)&bias[col];
            if (MODE == 3) {
                float2 ad = *(const float2*)&add[grow * CC + col];
                v0 += ad.x; v1 += ad.y;
            }
            float2 o;
            o.x = tanhf(v0 + bz.x);
            o.y = tanhf(v1 + bz.y);
            *(float2*)&O1[grow * CC + col] = o;
        }
    }
}

// ---------------- fused EA + EL/ELS GEMM (one X tile, two W matrices) ------
__global__ void __launch_bounds__(GEMM_THREADS, 1)
gemm12_k(const float* __restrict__ X,
         const float* __restrict__ W1,   // state_attention_W -> EA
         const float* __restrict__ W2,   // linked_state_attention_W -> EL
         const float* __restrict__ attb,
         float* __restrict__ OEA, __half* __restrict__ OT) {
    extern __shared__ __half sh[];
    __half* As  = sh;                      // TM x LDH
    __half* W1s = sh + TM * LDH;           // CC x LDH
    __half* W2s = sh + (TM + CC) * LDH;    // CC x LDH
    int t = threadIdx.x;
    int block_row = blockIdx.x * TM;

    const float4* W14 = (const float4*)W1;
    const float4* W24 = (const float4*)W2;
#pragma unroll
    for (int i = 0; i < 8; i++) {
        float4 v = W14[t + 512 * i];
        int e = (t + 512 * i) * 4;
        int r = e >> 7, c = e & 127;
        __half2* dst = (__half2*)&W1s[r * LDH + c];
        dst[0] = __floats2half2_rn(v.x, v.y);
        dst[1] = __floats2half2_rn(v.z, v.w);
        float4 u = W24[t + 512 * i];
        __half2* dst2 = (__half2*)&W2s[r * LDH + c];
        dst2[0] = __floats2half2_rn(u.x, u.y);
        dst2[1] = __floats2half2_rn(u.z, u.w);
    }
    const float4* X4 = (const float4*)(X + (size_t)block_row * CC);
#pragma unroll
    for (int i = 0; i < 4; i++) {
        float4 v = X4[t + 512 * i];
        int e = (t + 512 * i) * 4;
        int r = e >> 7, c = e & 127;
        __half2* dst = (__half2*)&As[r * LDH + c];
        dst[0] = __floats2half2_rn(v.x, v.y);
        dst[1] = __floats2half2_rn(v.z, v.w);
    }
    __syncthreads();

    int lane = t & 31, wid = t >> 5;
    int wm = (wid & 3) * 16;
    int wn = (wid >> 2) * 32;

    float accE[4][4], accL[4][4];
#pragma unroll
    for (int nf = 0; nf < 4; nf++)
#pragma unroll
        for (int q = 0; q < 4; q++) { accE[nf][q] = 0.f; accL[nf][q] = 0.f; }

    int a_row = wm + (lane & 15);
    int a_koff = (lane >> 4) << 3;
    int b_krow = ((lane >> 3) & 1) * 8 + (lane & 7);
    int b_noff = (lane >> 4) << 3;

#pragma unroll
    for (int ks = 0; ks < 8; ks++) {
        int kk = ks * 16;
        unsigned a0, a1, a2, a3;
        LDSM_X4(a0, a1, a2, a3, smem_u32(&As[a_row * LDH + kk + a_koff]));
#pragma unroll
        for (int nf = 0; nf < 4; nf += 2) {
            unsigned b0, b1, b2, b3;
            LDSM_X4T(b0, b1, b2, b3, smem_u32(&W1s[(kk + b_krow) * LDH + wn + nf * 8 + b_noff]));
            MMA16816(accE[nf],     a0, a1, a2, a3, b0, b1);
            MMA16816(accE[nf + 1], a0, a1, a2, a3, b2, b3);
            LDSM_X4T(b0, b1, b2, b3, smem_u32(&W2s[(kk + b_krow) * LDH + wn + nf * 8 + b_noff]));
            MMA16816(accL[nf],     a0, a1, a2, a3, b0, b1);
            MMA16816(accL[nf + 1], a0, a1, a2, a3, b2, b3);
        }
    }

    int lr0 = wm + (lane >> 2);
    int col_in = (lane & 3) * 2;
#pragma unroll
    for (int nf = 0; nf < 4; nf++) {
        int col = wn + nf * 8 + col_in;
#pragma unroll
        for (int half = 0; half < 2; half++) {
            int lrow = lr0 + half * 8;
            size_t grow = (size_t)(block_row + lrow);
            // EA
            float2 bz = *(const float2*)&attb[col];
            float2 oe;
            oe.x = __expf(accE[nf][half * 2 + 0] + bz.x);
            oe.y = __expf(accE[nf][half * 2 + 1] + bz.y);
            *(float2*)&OEA[grow * CC + col] = oe;
            // EL / ELS
            float el0 = __expf(accL[nf][half * 2 + 0]);
            float el1 = __expf(accL[nf][half * 2 + 1]);
            float s0 = __half2float(As[lrow * LDH + col]);
            float s1 = __half2float(As[lrow * LDH + col + 1]);
            __half2 e  = __floats2half2_rn(el0, el1);
            __half2 es = __floats2half2_rn(el0 * s0, el1 * s1);
            *(__half2*)&OT[grow * 2 * CC + col]      = e;
            *(__half2*)&OT[grow * 2 * CC + CC + col] = es;
        }
    }
}

// ---------------- per-node aggregation (one warp per node, no atomics) -----
__device__ __forceinline__ void acc8_fp16(float* acc, uint4 v) {
    unsigned int u[4] = {v.x, v.y, v.z, v.w};
#pragma unroll
    for (int q = 0; q < 4; q++) {
        float2 f = __half22float2(*(__half2*)&u[q]);
        acc[2 * q]     += f.x;
        acc[2 * q + 1] += f.y;
    }
}

__global__ void agg_kernel(const float* __restrict__ states) {
    int gw = (blockIdx.x * blockDim.x + threadIdx.x) >> 5;
    int lane = threadIdx.x & 31;
    if (gw >= M_TOTAL) return;
    int b = gw / NN;

    int deg = g_cur[gw];
    if (deg > STRIDE) deg = STRIDE;
    const int* __restrict__ adj = g_adj + (size_t)gw * STRIDE;
    const uint4* __restrict__ T4 = (const uint4*)(g_T + (size_t)b * NN * 2 * CC);

    float acc[8];
#pragma unroll
    for (int k = 0; k < 8; k++) acc[k] = 0.f;

    int e = 0;
    for (; e + 4 <= deg; e += 4) {
        int j0 = __ldg(adj + e);
        int j1 = __ldg(adj + e + 1);
        int j2 = __ldg(adj + e + 2);
        int j3 = __ldg(adj + e + 3);
        uint4 t0 = T4[(size_t)j0 * 32 + lane];
        uint4 t1 = T4[(size_t)j1 * 32 + lane];
        uint4 t2 = T4[(size_t)j2 * 32 + lane];
        uint4 t3 = T4[(size_t)j3 * 32 + lane];
        acc8_fp16(acc, t0);
        acc8_fp16(acc, t1);
        acc8_fp16(acc, t2);
        acc8_fp16(acc, t3);
    }
    for (; e < deg; e++) {
        int j = __ldg(adj + e);
        uint4 tv = T4[(size_t)j * 32 + lane];
        acc8_fp16(acc, tv);
    }

    float other[8];
#pragma unroll
    for (int k = 0; k < 8; k++)
        other[k] = __shfl_xor_sync(0xffffffffu, acc[k], 16);

    int sub = lane & 15;
    size_t rowf4 = (size_t)gw * 32 + sub * 2;
    float4 ea0 = ((const float4*)g_EA)[rowf4];
    float4 ea1 = ((const float4*)g_EA)[rowf4 + 1];
    float ea[8] = {ea0.x, ea0.y, ea0.z, ea0.w, ea1.x, ea1.y, ea1.z, ea1.w};

    float sE[8], sS[8];
    if (lane < 16) {
#pragma unroll
        for (int k = 0; k < 8; k++) { sE[k] = acc[k]; sS[k] = other[k]; }
    } else {
#pragma unroll
        for (int k = 0; k < 8; k++) { sE[k] = other[k]; sS[k] = acc[k]; }
    }

    float inv[8];
#pragma unroll
    for (int k = 0; k < 8; k++) inv[k] = 1.f / (1.f + ea[k] * sE[k]);

    if (lane < 16) {
        float4 G0, G1;
        G0.x = ea[0] * sS[0] * inv[0]; G0.y = ea[1] * sS[1] * inv[1];
        G0.z = ea[2] * sS[2] * inv[2]; G0.w = ea[3] * sS[3] * inv[3];
        G1.x = ea[4] * sS[4] * inv[4]; G1.y = ea[5] * sS[5] * inv[5];
        G1.z = ea[6] * sS[6] * inv[6]; G1.w = ea[7] * sS[7] * inv[7];
        ((float4*)g_G)[rowf4]     = G0;
        ((float4*)g_G)[rowf4 + 1] = G1;
    } else {
        float4 st0 = ((const float4*)states)[rowf4];
        float4 st1 = ((const float4*)states)[rowf4 + 1];
        float4 S0, S1;
        S0.x = st0.x * inv[0]; S0.y = st0.y * inv[1];
        S0.z = st0.z * inv[2]; S0.w = st0.w * inv[3];
        S1.x = st1.x * inv[4]; S1.y = st1.y * inv[5];
        S1.z = st1.z * inv[6]; S1.w = st1.w * inv[7];
        ((float4*)g_SS)[rowf4]     = S0;
        ((float4*)g_SS)[rowf4 + 1] = S1;
    }
}

// ---------------- launch ----------------------------------------------------
extern "C" void kernel_launch(void* const* d_in, const int* in_sizes, int n_in,
                              void* d_out, int out_size) {
    const float* objects = (const float*)d_in[0];
    const float* Wos     = (const float*)d_in[1];
    const float* Wsa     = (const float*)d_in[2];
    const float* Wla     = (const float*)d_in[3];
    const float* att_b   = (const float*)d_in[4];
    const float* Wl      = (const float*)d_in[5];
    const float* st_b    = (const float*)d_in[6];
    const int*   conn    = (const int*)d_in[7];
    float* states = (float*)d_out;            // live states buffer, [B,N,C]

    cudaFuncSetAttribute(gemm_k<0>, cudaFuncAttributeMaxDynamicSharedMemorySize, GEMM_SMEM_BYTES);
    cudaFuncSetAttribute(gemm_k<3>, cudaFuncAttributeMaxDynamicSharedMemorySize, GEMM_SMEM_BYTES);
    cudaFuncSetAttribute(gemm12_k, cudaFuncAttributeMaxDynamicSharedMemorySize, GEMM12_SMEM_BYTES);

    float *pEA, *pG, *pSS;
    __half* pT;
    cudaGetSymbolAddress((void**)&pEA, g_EA);
    cudaGetSymbolAddress((void**)&pT,  g_T);
    cudaGetSymbolAddress((void**)&pG,  g_G);
    cudaGetSymbolAddress((void**)&pSS, g_SS);

    const int EDGE_BLOCKS = (BB * EE + 255) / 256;      // 2500
    const int GEMM_GRID   = M_TOTAL / TM;               // 625
    const int AGG_GRID    = (M_TOTAL * 32 + 255) / 256; // 5000

    // ELL build (per launch; connections are an input)
    zero_cur_kernel<<<(M_TOTAL + 255) / 256, 256>>>();
    fill_kernel<<<EDGE_BLOCKS, 256>>>(conn);

    // init states = tanh(objects @ Wos + st_b)
    gemm_k<0><<<GEMM_GRID, GEMM_THREADS, GEMM_SMEM_BYTES>>>(objects, Wos, st_b, nullptr, states);

    for (int it = 0; it < ITERS; it++) {
        gemm12_k<<<GEMM_GRID, GEMM_THREADS, GEMM12_SMEM_BYTES>>>(states, Wsa, Wla, att_b, pEA, pT);
        agg_kernel<<<AGG_GRID, 256>>>(states);
        gemm_k<3><<<GEMM_GRID, GEMM_THREADS, GEMM_SMEM_BYTES>>>(pG, Wl, st_b, pSS, states);
    }
}

// round 12
// speedup vs baseline: 2.3443x; 1.0475x over previous
#include <cuda_runtime.h>
#include <cuda_fp16.h>
#include <math.h>

#define BB 4
#define NN 10000
#define EE 160000
#define CC 128
#define ITERS 3
#define M_TOTAL (BB * NN)          // 40000 rows
#define TM 64
#define NTILES (M_TOTAL / TM)      // 625
#define LDH 136                    // padded smem stride in halves (272B)
#define GEMM_THREADS 512
#define GEMM_SMEM_BYTES ((TM + CC) * LDH * 2)        // 52224 B
#define GEMM12_SMEM_BYTES ((TM + 2 * CC) * LDH * 2)  // 87040 B
#define PGRID 148                  // persistent grid: one CTA per SM
#define STRIDE 128                 // ELL slots per node (mean degree 32)

// ---------------- scratch (static device globals; no runtime allocation) ----
__device__ __align__(16) float g_EA [M_TOTAL * CC];      // exp(states@Wsa + att_b)
__device__ __align__(16) __half g_T[M_TOTAL * 2 * CC];   // per node: [EL(128) | ELS(128)] fp16
__device__ __align__(16) float g_G  [M_TOTAL * CC];      // linked_gated
__device__ __align__(16) float g_SS [M_TOTAL * CC];      // states / norm
__device__ int g_cur[M_TOTAL];                           // fill cursor == degree after fill
__device__ int g_adj[M_TOTAL * STRIDE];                  // ELL adjacency

// ---------------- ELL build ------------------------------------------------
__global__ void zero_cur_kernel() {
    int i = blockIdx.x * blockDim.x + threadIdx.x;
    if (i < M_TOTAL) g_cur[i] = 0;
}

__global__ void fill_kernel(const int* __restrict__ conn) {
    int idx = blockIdx.x * blockDim.x + threadIdx.x;
    if (idx >= BB * EE) return;
    int b = idx / EE;
    int2 uv = ((const int2*)conn)[idx];
    int nu = b * NN + uv.x, nv = b * NN + uv.y;
    int p = atomicAdd(&g_cur[nu], 1);
    if (p < STRIDE) g_adj[(size_t)nu * STRIDE + p] = uv.y;
    int q = atomicAdd(&g_cur[nv], 1);
    if (q < STRIDE) g_adj[(size_t)nv * STRIDE + q] = uv.x;
}

// ---------------- mma.sync helpers -----------------------------------------
__device__ __forceinline__ unsigned smem_u32(const void* p) {
    return (unsigned)__cvta_generic_to_shared(p);
}

#define LDSM_X4(r0, r1, r2, r3, addr) \
    asm volatile("ldmatrix.sync.aligned.m8n8.x4.shared.b16 {%0,%1,%2,%3}, [%4];" \
                 : "=r"(r0), "=r"(r1), "=r"(r2), "=r"(r3) : "r"(addr))
#define LDSM_X4T(r0, r1, r2, r3, addr) \
    asm volatile("ldmatrix.sync.aligned.m8n8.x4.trans.shared.b16 {%0,%1,%2,%3}, [%4];" \
                 : "=r"(r0), "=r"(r1), "=r"(r2), "=r"(r3) : "r"(addr))
#define MMA16816(acc, a0, a1, a2, a3, b0, b1) \
    asm volatile("mma.sync.aligned.m16n8k16.row.col.f32.f16.f16.f32 " \
                 "{%0,%1,%2,%3}, {%4,%5,%6,%7}, {%8,%9}, {%0,%1,%2,%3};" \
                 : "+f"(acc[0]), "+f"(acc[1]), "+f"(acc[2]), "+f"(acc[3]) \
                 : "r"(a0), "r"(a1), "r"(a2), "r"(a3), "r"(b0), "r"(b1))

// store 4 float4 (one X row-chunk per thread) into fp16 smem tile
__device__ __forceinline__ void stash_X(__half* As, const float4* rX, int t) {
#pragma unroll
    for (int i = 0; i < 4; i++) {
        int e = (t + 512 * i) * 4;
        int r = e >> 7, c = e & 127;
        __half2* dst = (__half2*)&As[r * LDH + c];
        dst[0] = __floats2half2_rn(rX[i].x, rX[i].y);
        dst[1] = __floats2half2_rn(rX[i].z, rX[i].w);
    }
}

// ---------------- persistent GEMM [40000,128]x[128,128] via mma.sync fp16 --
// W resident in smem for kernel lifetime; CTA loops over tiles (stride PGRID).
// Next tile's X is preloaded into registers before the epilogue.
// MODE 0: O1 = tanh(acc + bias)       MODE 3: O1 = tanh(acc + add + bias)
template <int MODE>
__global__ void __launch_bounds__(GEMM_THREADS, 1)
gemm_k(const float* __restrict__ X, const float* __restrict__ W,
       const float* __restrict__ bias, const float* __restrict__ add,
       float* __restrict__ O1) {
    extern __shared__ __half sh[];
    __half* As  = sh;                 // TM x LDH
    __half* Wsh = sh + TM * LDH;      // CC x LDH
    int t = threadIdx.x;

    // load + convert W once
    const float4* W4 = (const float4*)W;
#pragma unroll
    for (int i = 0; i < 8; i++) {
        float4 v = W4[t + 512 * i];
        int e = (t + 512 * i) * 4;
        int r = e >> 7, c = e & 127;
        __half2* dst = (__half2*)&Wsh[r * LDH + c];
        dst[0] = __floats2half2_rn(v.x, v.y);
        dst[1] = __floats2half2_rn(v.z, v.w);
    }

    int lane = t & 31, wid = t >> 5;
    int wm = (wid & 3) * 16;
    int wn = (wid >> 2) * 32;
    int a_row = wm + (lane & 15);
    int a_koff = (lane >> 4) << 3;
    int b_krow = ((lane >> 3) & 1) * 8 + (lane & 7);
    int b_noff = (lane >> 4) << 3;
    int lr0 = wm + (lane >> 2);
    int col_in = (lane & 3) * 2;

    // preload first tile's X
    float4 rX[4];
    int tile = blockIdx.x;
    if (tile < NTILES) {
        const float4* X4 = (const float4*)(X + (size_t)tile * TM * CC);
#pragma unroll
        for (int i = 0; i < 4; i++) rX[i] = X4[t + 512 * i];
    }

    for (; tile < NTILES; tile += PGRID) {
        __syncthreads();                  // As free (prev mainloop+epilogue done)
        stash_X(As, rX, t);
        __syncthreads();

        float acc[4][4];
#pragma unroll
        for (int nf = 0; nf < 4; nf++)
#pragma unroll
            for (int q = 0; q < 4; q++) acc[nf][q] = 0.f;

#pragma unroll
        for (int ks = 0; ks < 8; ks++) {
            int kk = ks * 16;
            unsigned a0, a1, a2, a3;
            LDSM_X4(a0, a1, a2, a3, smem_u32(&As[a_row * LDH + kk + a_koff]));
#pragma unroll
            for (int nf = 0; nf < 4; nf += 2) {
                unsigned b0, b1, b2, b3;
                LDSM_X4T(b0, b1, b2, b3, smem_u32(&Wsh[(kk + b_krow) * LDH + wn + nf * 8 + b_noff]));
                MMA16816(acc[nf],     a0, a1, a2, a3, b0, b1);
                MMA16816(acc[nf + 1], a0, a1, a2, a3, b2, b3);
            }
        }

        // issue next tile's X loads (latency hides under epilogue)
        int next = tile + PGRID;
        if (next < NTILES) {
            const float4* X4 = (const float4*)(X + (size_t)next * TM * CC);
#pragma unroll
            for (int i = 0; i < 4; i++) rX[i] = X4[t + 512 * i];
        }

        int block_row = tile * TM;
#pragma unroll
        for (int nf = 0; nf < 4; nf++) {
            int col = wn + nf * 8 + col_in;
#pragma unroll
            for (int half = 0; half < 2; half++) {
                int lrow = lr0 + half * 8;
                size_t grow = (size_t)(block_row + lrow);
                float v0 = acc[nf][half * 2 + 0];
                float v1 = acc[nf][half * 2 + 1];
                float2 bz = *(const float2*)&bias[col];
                if (MODE == 3) {
                    float2 ad = *(const float2*)&add[grow * CC + col];
                    v0 += ad.x; v1 += ad.y;
                }
                float2 o;
                o.x = tanhf(v0 + bz.x);
                o.y = tanhf(v1 + bz.y);
                *(float2*)&O1[grow * CC + col] = o;
            }
        }
    }
}

// ---------------- persistent fused EA + EL/ELS GEMM ------------------------
__global__ void __launch_bounds__(GEMM_THREADS, 1)
gemm12_k(const float* __restrict__ X,
         const float* __restrict__ W1,   // state_attention_W -> EA
         const float* __restrict__ W2,   // linked_state_attention_W -> EL
         const float* __restrict__ attb,
         float* __restrict__ OEA, __half* __restrict__ OT) {
    extern __shared__ __half sh[];
    __half* As  = sh;                      // TM x LDH
    __half* W1s = sh + TM * LDH;           // CC x LDH
    __half* W2s = sh + (TM + CC) * LDH;    // CC x LDH
    int t = threadIdx.x;

    const float4* W14 = (const float4*)W1;
    const float4* W24 = (const float4*)W2;
#pragma unroll
    for (int i = 0; i < 8; i++) {
        float4 v = W14[t + 512 * i];
        int e = (t + 512 * i) * 4;
        int r = e >> 7, c = e & 127;
        __half2* dst = (__half2*)&W1s[r * LDH + c];
        dst[0] = __floats2half2_rn(v.x, v.y);
        dst[1] = __floats2half2_rn(v.z, v.w);
        float4 u = W24[t + 512 * i];
        __half2* dst2 = (__half2*)&W2s[r * LDH + c];
        dst2[0] = __floats2half2_rn(u.x, u.y);
        dst2[1] = __floats2half2_rn(u.z, u.w);
    }

    int lane = t & 31, wid = t >> 5;
    int wm = (wid & 3) * 16;
    int wn = (wid >> 2) * 32;
    int a_row = wm + (lane & 15);
    int a_koff = (lane >> 4) << 3;
    int b_krow = ((lane >> 3) & 1) * 8 + (lane & 7);
    int b_noff = (lane >> 4) << 3;
    int lr0 = wm + (lane >> 2);
    int col_in = (lane & 3) * 2;

    float4 rX[4];
    int tile = blockIdx.x;
    if (tile < NTILES) {
        const float4* X4 = (const float4*)(X + (size_t)tile * TM * CC);
#pragma unroll
        for (int i = 0; i < 4; i++) rX[i] = X4[t + 512 * i];
    }

    for (; tile < NTILES; tile += PGRID) {
        __syncthreads();
        stash_X(As, rX, t);
        __syncthreads();

        float accE[4][4], accL[4][4];
#pragma unroll
        for (int nf = 0; nf < 4; nf++)
#pragma unroll
            for (int q = 0; q < 4; q++) { accE[nf][q] = 0.f; accL[nf][q] = 0.f; }

#pragma unroll
        for (int ks = 0; ks < 8; ks++) {
            int kk = ks * 16;
            unsigned a0, a1, a2, a3;
            LDSM_X4(a0, a1, a2, a3, smem_u32(&As[a_row * LDH + kk + a_koff]));
#pragma unroll
            for (int nf = 0; nf < 4; nf += 2) {
                unsigned b0, b1, b2, b3;
                LDSM_X4T(b0, b1, b2, b3, smem_u32(&W1s[(kk + b_krow) * LDH + wn + nf * 8 + b_noff]));
                MMA16816(accE[nf],     a0, a1, a2, a3, b0, b1);
                MMA16816(accE[nf + 1], a0, a1, a2, a3, b2, b3);
                LDSM_X4T(b0, b1, b2, b3, smem_u32(&W2s[(kk + b_krow) * LDH + wn + nf * 8 + b_noff]));
                MMA16816(accL[nf],     a0, a1, a2, a3, b0, b1);
                MMA16816(accL[nf + 1], a0, a1, a2, a3, b2, b3);
            }
        }

        int next = tile + PGRID;
        if (next < NTILES) {
            const float4* X4 = (const float4*)(X + (size_t)next * TM * CC);
            // NOTE: rX still needed by MODE-2 epilogue? No — epilogue reads As, not rX.
#pragma unroll
            for (int i = 0; i < 4; i++) rX[i] = X4[t + 512 * i];
        }

        int block_row = tile * TM;
#pragma unroll
        for (int nf = 0; nf < 4; nf++) {
            int col = wn + nf * 8 + col_in;
#pragma unroll
            for (int half = 0; half < 2; half++) {
                int lrow = lr0 + half * 8;
                size_t grow = (size_t)(block_row + lrow);
                // EA
                float2 bz = *(const float2*)&attb[col];
                float2 oe;
                oe.x = __expf(accE[nf][half * 2 + 0] + bz.x);
                oe.y = __expf(accE[nf][half * 2 + 1] + bz.y);
                *(float2*)&OEA[grow * CC + col] = oe;
                // EL / ELS (states read from As)
                float el0 = __expf(accL[nf][half * 2 + 0]);
                float el1 = __expf(accL[nf][half * 2 + 1]);
                float s0 = __half2float(As[lrow * LDH + col]);
                float s1 = __half2float(As[lrow * LDH + col + 1]);
                __half2 e  = __floats2half2_rn(el0, el1);
                __half2 es = __floats2half2_rn(el0 * s0, el1 * s1);
                *(__half2*)&OT[grow * 2 * CC + col]      = e;
                *(__half2*)&OT[grow * 2 * CC + CC + col] = es;
            }
        }
    }
}

// ---------------- per-node aggregation (one warp per node, no atomics) -----
__device__ __forceinline__ void acc8_fp16(float* acc, uint4 v) {
    unsigned int u[4] = {v.x, v.y, v.z, v.w};
#pragma unroll
    for (int q = 0; q < 4; q++) {
        float2 f = __half22float2(*(__half2*)&u[q]);
        acc[2 * q]     += f.x;
        acc[2 * q + 1] += f.y;
    }
}

__global__ void agg_kernel(const float* __restrict__ states) {
    int gw = (blockIdx.x * blockDim.x + threadIdx.x) >> 5;
    int lane = threadIdx.x & 31;
    if (gw >= M_TOTAL) return;
    int b = gw / NN;

    int deg = g_cur[gw];
    if (deg > STRIDE) deg = STRIDE;
    const int* __restrict__ adj = g_adj + (size_t)gw * STRIDE;
    const uint4* __restrict__ T4 = (const uint4*)(g_T + (size_t)b * NN * 2 * CC);

    float acc[8];
#pragma unroll
    for (int k = 0; k < 8; k++) acc[k] = 0.f;

    int e = 0;
    for (; e + 4 <= deg; e += 4) {
        int j0 = __ldg(adj + e);
        int j1 = __ldg(adj + e + 1);
        int j2 = __ldg(adj + e + 2);
        int j3 = __ldg(adj + e + 3);
        uint4 t0 = T4[(size_t)j0 * 32 + lane];
        uint4 t1 = T4[(size_t)j1 * 32 + lane];
        uint4 t2 = T4[(size_t)j2 * 32 + lane];
        uint4 t3 = T4[(size_t)j3 * 32 + lane];
        acc8_fp16(acc, t0);
        acc8_fp16(acc, t1);
        acc8_fp16(acc, t2);
        acc8_fp16(acc, t3);
    }
    for (; e < deg; e++) {
        int j = __ldg(adj + e);
        uint4 tv = T4[(size_t)j * 32 + lane];
        acc8_fp16(acc, tv);
    }

    float other[8];
#pragma unroll
    for (int k = 0; k < 8; k++)
        other[k] = __shfl_xor_sync(0xffffffffu, acc[k], 16);

    int sub = lane & 15;
    size_t rowf4 = (size_t)gw * 32 + sub * 2;
    float4 ea0 = ((const float4*)g_EA)[rowf4];
    float4 ea1 = ((const float4*)g_EA)[rowf4 + 1];
    float ea[8] = {ea0.x, ea0.y, ea0.z, ea0.w, ea1.x, ea1.y, ea1.z, ea1.w};

    float sE[8], sS[8];
    if (lane < 16) {
#pragma unroll
        for (int k = 0; k < 8; k++) { sE[k] = acc[k]; sS[k] = other[k]; }
    } else {
#pragma unroll
        for (int k = 0; k < 8; k++) { sE[k] = other[k]; sS[k] = acc[k]; }
    }

    float inv[8];
#pragma unroll
    for (int k = 0; k < 8; k++) inv[k] = 1.f / (1.f + ea[k] * sE[k]);

    if (lane < 16) {
        float4 G0, G1;
        G0.x = ea[0] * sS[0] * inv[0]; G0.y = ea[1] * sS[1] * inv[1];
        G0.z = ea[2] * sS[2] * inv[2]; G0.w = ea[3] * sS[3] * inv[3];
        G1.x = ea[4] * sS[4] * inv[4]; G1.y = ea[5] * sS[5] * inv[5];
        G1.z = ea[6] * sS[6] * inv[6]; G1.w = ea[7] * sS[7] * inv[7];
        ((float4*)g_G)[rowf4]     = G0;
        ((float4*)g_G)[rowf4 + 1] = G1;
    } else {
        float4 st0 = ((const float4*)states)[rowf4];
        float4 st1 = ((const float4*)states)[rowf4 + 1];
        float4 S0, S1;
        S0.x = st0.x * inv[0]; S0.y = st0.y * inv[1];
        S0.z = st0.z * inv[2]; S0.w = st0.w * inv[3];
        S1.x = st1.x * inv[4]; S1.y = st1.y * inv[5];
        S1.z = st1.z * inv[6]; S1.w = st1.w * inv[7];
        ((float4*)g_SS)[rowf4]     = S0;
        ((float4*)g_SS)[rowf4 + 1] = S1;
    }
}

// ---------------- launch ----------------------------------------------------
extern "C" void kernel_launch(void* const* d_in, const int* in_sizes, int n_in,
                              void* d_out, int out_size) {
    const float* objects = (const float*)d_in[0];
    const float* Wos     = (const float*)d_in[1];
    const float* Wsa     = (const float*)d_in[2];
    const float* Wla     = (const float*)d_in[3];
    const float* att_b   = (const float*)d_in[4];
    const float* Wl      = (const float*)d_in[5];
    const float* st_b    = (const float*)d_in[6];
    const int*   conn    = (const int*)d_in[7];
    float* states = (float*)d_out;            // live states buffer, [B,N,C]

    cudaFuncSetAttribute(gemm_k<0>, cudaFuncAttributeMaxDynamicSharedMemorySize, GEMM_SMEM_BYTES);
    cudaFuncSetAttribute(gemm_k<3>, cudaFuncAttributeMaxDynamicSharedMemorySize, GEMM_SMEM_BYTES);
    cudaFuncSetAttribute(gemm12_k, cudaFuncAttributeMaxDynamicSharedMemorySize, GEMM12_SMEM_BYTES);

    float *pEA, *pG, *pSS;
    __half* pT;
    cudaGetSymbolAddress((void**)&pEA, g_EA);
    cudaGetSymbolAddress((void**)&pT,  g_T);
    cudaGetSymbolAddress((void**)&pG,  g_G);
    cudaGetSymbolAddress((void**)&pSS, g_SS);

    const int EDGE_BLOCKS = (BB * EE + 255) / 256;      // 2500
    const int AGG_GRID    = (M_TOTAL * 32 + 255) / 256; // 5000

    // ELL build (per launch; connections are an input)
    zero_cur_kernel<<<(M_TOTAL + 255) / 256, 256>>>();
    fill_kernel<<<EDGE_BLOCKS, 256>>>(conn);

    // init states = tanh(objects @ Wos + st_b)
    gemm_k<0><<<PGRID, GEMM_THREADS, GEMM_SMEM_BYTES>>>(objects, Wos, st_b, nullptr, states);

    for (int it = 0; it < ITERS; it++) {
        gemm12_k<<<PGRID, GEMM_THREADS, GEMM12_SMEM_BYTES>>>(states, Wsa, Wla, att_b, pEA, pT);
        agg_kernel<<<AGG_GRID, 256>>>(states);
        gemm_k<3><<<PGRID, GEMM_THREADS, GEMM_SMEM_BYTES>>>(pG, Wl, st_b, pSS, states);
    }
}